// round 3
// baseline (speedup 1.0000x reference)
#include <cuda_runtime.h>
#include <cuda_bf16.h>
#include <math.h>

#define BB 32
#define TT 64
#define SS 400
#define HH 256
#define EE 128
#define VV 50000
#define H2 512

// d_out layout (fp32): vocab_dists[B,T,V], attn[B,T,S], pgen[B,T,1], h[B,H], c[B,H]
#define OFF_ATTN 102400000ull
#define OFF_PG   103219200ull
#define OFF_H    103221248ull
#define OFF_C    103229440ull

// ---------------- scratch (static device memory; no allocation) ----------------
__device__ float g_enc_feat[BB * SS * HH];    // 13.1 MB
__device__ float g_hbuf[2][BB * HH];
__device__ float g_cbuf[2][BB * HH];
__device__ float g_ctx[BB * H2];
__device__ float g_x[BB * HH];
__device__ float g_dec[BB * HH];
__device__ float g_scores[BB * SS];
__device__ float g_vred[BB * TT * HH];        // 2 MB, rows ordered r=b*T+t

__device__ __forceinline__ float sigf(float v) { return 1.0f / (1.0f + expf(-v)); }

// ---------------- init ----------------
__global__ void k_init(const float* __restrict__ h0, const float* __restrict__ c0,
                       float* __restrict__ hA, float* __restrict__ cA,
                       float* __restrict__ ctx) {
    int i = blockIdx.x * 256 + threadIdx.x;
    if (i < BB * HH) { hA[i] = h0[i]; cA[i] = c0[i]; }
    if (i < BB * H2) ctx[i] = 0.0f;
}

// ---------------- generic fp32 GEMM: C[M,N] = A[M,K] @ Bw[N,K]^T + bias ----------------
// BM=BN=128, BK=8, 256 threads, 8x8 per thread. M%128==0, K%8==0 required; N guarded.
__global__ __launch_bounds__(256) void sgemm_abt(
    const float* __restrict__ A, const float* __restrict__ Bw,
    const float* __restrict__ bias, float* __restrict__ C,
    int M, int N, int K)
{
    __shared__ float As[8][128];
    __shared__ float Bs[8][128];
    const int tid = threadIdx.x;
    const int row0 = blockIdx.y << 7;
    const int col0 = blockIdx.x << 7;
    const int tr = (tid >> 4) << 3;
    const int tc = (tid & 15) << 3;
    float acc[8][8];
#pragma unroll
    for (int i = 0; i < 8; i++)
#pragma unroll
        for (int j = 0; j < 8; j++) acc[i][j] = 0.0f;

    const int lr = tid >> 1;            // 0..127
    const int lk = (tid & 1) << 2;      // 0 or 4
    const bool bok = (col0 + lr) < N;

    for (int k0 = 0; k0 < K; k0 += 8) {
        float4 av = *(const float4*)&A[(size_t)(row0 + lr) * K + k0 + lk];
        float4 bv = bok ? *(const float4*)&Bw[(size_t)(col0 + lr) * K + k0 + lk]
                        : make_float4(0.f, 0.f, 0.f, 0.f);
        As[lk + 0][lr] = av.x; As[lk + 1][lr] = av.y; As[lk + 2][lr] = av.z; As[lk + 3][lr] = av.w;
        Bs[lk + 0][lr] = bv.x; Bs[lk + 1][lr] = bv.y; Bs[lk + 2][lr] = bv.z; Bs[lk + 3][lr] = bv.w;
        __syncthreads();
#pragma unroll
        for (int kk = 0; kk < 8; kk++) {
            float4 a0 = *(const float4*)&As[kk][tr];
            float4 a1 = *(const float4*)&As[kk][tr + 4];
            float4 b0 = *(const float4*)&Bs[kk][tc];
            float4 b1 = *(const float4*)&Bs[kk][tc + 4];
            float a[8] = {a0.x, a0.y, a0.z, a0.w, a1.x, a1.y, a1.z, a1.w};
            float b[8] = {b0.x, b0.y, b0.z, b0.w, b1.x, b1.y, b1.z, b1.w};
#pragma unroll
            for (int i = 0; i < 8; i++)
#pragma unroll
                for (int j = 0; j < 8; j++) acc[i][j] += a[i] * b[j];
        }
        __syncthreads();
    }
#pragma unroll
    for (int i = 0; i < 8; i++) {
        size_t r = row0 + tr + i;
#pragma unroll
        for (int j = 0; j < 8; j++) {
            int c = col0 + tc + j;
            if (c < N) C[r * (size_t)N + c] = acc[i][j] + (bias ? bias[c] : 0.0f);
        }
    }
}

// ---------------- x = [emb_t, ctx] @ Wr^T + br ----------------
// grid 32 blocks x 256 threads; thread = (b = tid&31, nl = tid>>5); n = blk*8+nl
__global__ __launch_bounds__(256) void k_x(
    const int* __restrict__ ids, const float* __restrict__ emb,
    const float* __restrict__ ctx, const float* __restrict__ Wr,
    const float* __restrict__ br, float* __restrict__ xout, int t)
{
    __shared__ float sA[128 * 33];
    const int tid = threadIdx.x;
    const int b = tid & 31, nl = tid >> 5;
    const int n = (blockIdx.x << 3) + nl;
    const float* wrow = Wr + (size_t)n * 640;
    float acc = 0.0f;
    for (int k0 = 0; k0 < 640; k0 += 128) {
        for (int i = tid; i < 4096; i += 256) {
            int bb = i >> 7, kk = i & 127;
            int k = k0 + kk;
            float v;
            if (k < EE) v = emb[(size_t)ids[bb * TT + t] * EE + k];
            else        v = ctx[bb * H2 + (k - EE)];
            sA[kk * 33 + bb] = v;
        }
        __syncthreads();
        const float4* w4 = (const float4*)(wrow + k0);
#pragma unroll 8
        for (int q = 0; q < 32; q++) {
            float4 w = w4[q];
            int kb = q * 4;
            acc += sA[(kb + 0) * 33 + b] * w.x + sA[(kb + 1) * 33 + b] * w.y
                 + sA[(kb + 2) * 33 + b] * w.z + sA[(kb + 3) * 33 + b] * w.w;
        }
        __syncthreads();
    }
    xout[b * HH + n] = acc + br[n];
}

// ---------------- gates + LSTM elementwise ----------------
__global__ __launch_bounds__(256) void k_gates(
    const float* __restrict__ x, const float* __restrict__ hin,
    const float* __restrict__ cin,
    const float* __restrict__ Wih, const float* __restrict__ Whh,
    const float* __restrict__ bih, const float* __restrict__ bhh,
    float* __restrict__ hout, float* __restrict__ cout)
{
    __shared__ float sA[128 * 33];
    const int tid = threadIdx.x;
    const int b = tid & 31, jl = tid >> 5;
    const int j = (blockIdx.x << 3) + jl;
    float acc0 = 0.f, acc1 = 0.f, acc2 = 0.f, acc3 = 0.f;
    for (int k0 = 0; k0 < 512; k0 += 128) {
        for (int i = tid; i < 4096; i += 256) {
            int bb = i >> 7, kk = i & 127;
            int k = k0 + kk;
            sA[kk * 33 + bb] = (k < HH) ? x[bb * HH + k] : hin[bb * HH + k - HH];
        }
        __syncthreads();
        const float* W = (k0 < 256) ? Wih : Whh;
        int koff = k0 & 255;
        const float4* w0 = (const float4*)(W + (size_t)(j) * 256 + koff);
        const float4* w1 = (const float4*)(W + (size_t)(256 + j) * 256 + koff);
        const float4* w2 = (const float4*)(W + (size_t)(512 + j) * 256 + koff);
        const float4* w3 = (const float4*)(W + (size_t)(768 + j) * 256 + koff);
#pragma unroll 4
        for (int q = 0; q < 32; q++) {
            int kb = q * 4;
            float a0 = sA[(kb + 0) * 33 + b], a1 = sA[(kb + 1) * 33 + b];
            float a2 = sA[(kb + 2) * 33 + b], a3 = sA[(kb + 3) * 33 + b];
            float4 w;
            w = w0[q]; acc0 += a0 * w.x + a1 * w.y + a2 * w.z + a3 * w.w;
            w = w1[q]; acc1 += a0 * w.x + a1 * w.y + a2 * w.z + a3 * w.w;
            w = w2[q]; acc2 += a0 * w.x + a1 * w.y + a2 * w.z + a3 * w.w;
            w = w3[q]; acc3 += a0 * w.x + a1 * w.y + a2 * w.z + a3 * w.w;
        }
        __syncthreads();
    }
    float gi = acc0 + bih[j]       + bhh[j];
    float gf = acc1 + bih[256 + j] + bhh[256 + j];
    float gg = acc2 + bih[512 + j] + bhh[512 + j];
    float go = acc3 + bih[768 + j] + bhh[768 + j];
    float co = cin[b * HH + j];
    float cn = sigf(gf) * co + sigf(gi) * tanhf(gg);
    float hn = sigf(go) * tanhf(cn);
    cout[b * HH + j] = cn;
    hout[b * HH + j] = hn;
}

// ---------------- generic 32-row linear: out = [s1|s2] @ W^T + bias ----------------
__global__ __launch_bounds__(256) void k_rowlin(
    const float* __restrict__ s1, int L1,
    const float* __restrict__ s2, int L2,
    const float* __restrict__ W, int Kw,
    const float* __restrict__ bias,
    float* __restrict__ out, int outStride)
{
    __shared__ float sA[128 * 33];
    const int tid = threadIdx.x;
    const int b = tid & 31, nl = tid >> 5;
    const int n = (blockIdx.x << 3) + nl;
    const float* wrow = W + (size_t)n * Kw;
    float acc = 0.0f;
    for (int k0 = 0; k0 < Kw; k0 += 128) {
        for (int i = tid; i < 4096; i += 256) {
            int bb = i >> 7, kk = i & 127;
            int k = k0 + kk;
            sA[kk * 33 + bb] = (k < L1) ? s1[bb * L1 + k] : s2[bb * L2 + k - L1];
        }
        __syncthreads();
        const float4* w4 = (const float4*)(wrow + k0);
#pragma unroll 4
        for (int q = 0; q < 32; q++) {
            int kb = q * 4;
            float4 w = w4[q];
            acc += sA[(kb + 0) * 33 + b] * w.x + sA[(kb + 1) * 33 + b] * w.y
                 + sA[(kb + 2) * 33 + b] * w.z + sA[(kb + 3) * 33 + b] * w.w;
        }
        __syncthreads();
    }
    out[b * outStride + n] = acc + bias[n];
}

// ---------------- attention scores ----------------
// grid (50, 32), 256 threads: warp w -> position s = blk*8+w, lanes split k.
__global__ __launch_bounds__(256) void k_scores(
    const float* __restrict__ enc_feat, const float* __restrict__ dec,
    const float* __restrict__ va, const unsigned char* __restrict__ mask,
    float* __restrict__ scores)
{
    __shared__ float sdf[256], sva[256];
    const int b = blockIdx.y;
    const int tid = threadIdx.x;
    sdf[tid] = dec[b * HH + tid];
    sva[tid] = va[tid];
    __syncthreads();
    const int w = tid >> 5, lane = tid & 31;
    const int s = blockIdx.x * 8 + w;
    const float4* ef = (const float4*)(enc_feat + ((size_t)b * SS + s) * HH);
    float acc = 0.0f;
#pragma unroll
    for (int h = 0; h < 2; h++) {
        int k4 = lane + h * 32;
        float4 e = ef[k4];
        float4 d = ((const float4*)sdf)[k4];
        float4 v = ((const float4*)sva)[k4];
        acc += v.x * tanhf(e.x + d.x) + v.y * tanhf(e.y + d.y)
             + v.z * tanhf(e.z + d.z) + v.w * tanhf(e.w + d.w);
    }
#pragma unroll
    for (int o = 16; o > 0; o >>= 1) acc += __shfl_xor_sync(0xffffffffu, acc, o);
    if (lane == 0) {
        scores[b * SS + s] = mask[b * SS + s] ? -INFINITY : acc;
    }
}

// ---------------- softmax over S + ctx + pgen (grid 32, 512 threads) ----------------
__global__ __launch_bounds__(512) void k_attn_ctx(
    const float* __restrict__ scores, const float* __restrict__ enc,
    const float* __restrict__ hn, const float* __restrict__ cn,
    const float* __restrict__ x,
    const float* __restrict__ whp, const float* __restrict__ wsp,
    const float* __restrict__ wxp, const float* __restrict__ bxp,
    float* __restrict__ ctx_out, float* __restrict__ dout, int t)
{
    __shared__ float sattn[SS];
    __shared__ float red[512];
    __shared__ float sctx[512];
    const int b = blockIdx.x, tid = threadIdx.x;

    float sc = (tid < SS) ? scores[b * SS + tid] : -INFINITY;
    red[tid] = sc;
    __syncthreads();
#pragma unroll
    for (int o = 256; o > 0; o >>= 1) {
        if (tid < o) red[tid] = fmaxf(red[tid], red[tid + o]);
        __syncthreads();
    }
    float m = red[0];
    __syncthreads();
    float e = (tid < SS) ? expf(sc - m) : 0.0f;
    red[tid] = e;
    __syncthreads();
#pragma unroll
    for (int o = 256; o > 0; o >>= 1) {
        if (tid < o) red[tid] += red[tid + o];
        __syncthreads();
    }
    float inv = 1.0f / red[0];
    __syncthreads();
    if (tid < SS) {
        float a = e * inv;
        sattn[tid] = a;
        dout[OFF_ATTN + ((size_t)b * TT + t) * SS + tid] = a;
    }
    __syncthreads();

    // ctx: 128 threads, float4 each covering 4 of 512 dims
    if (tid < 128) {
        const float4* ep = (const float4*)(enc + (size_t)b * SS * H2);
        float4 a4 = make_float4(0.f, 0.f, 0.f, 0.f);
#pragma unroll 4
        for (int s = 0; s < SS; s++) {
            float w = sattn[s];
            float4 v = ep[(size_t)s * 128 + tid];
            a4.x += w * v.x; a4.y += w * v.y; a4.z += w * v.z; a4.w += w * v.w;
        }
        ((float4*)(ctx_out + b * H2))[tid] = a4;
        int k4 = tid * 4;
        sctx[k4 + 0] = a4.x; sctx[k4 + 1] = a4.y; sctx[k4 + 2] = a4.z; sctx[k4 + 3] = a4.w;
    }
    __syncthreads();

    // pgen = sigmoid(wh_p.ctx + ws_p.[h,c] + wx_p.x + bx_p)
    float scv = (tid < HH) ? hn[b * HH + tid] : cn[b * HH + (tid - HH)];
    float p = whp[tid] * sctx[tid] + wsp[tid] * scv
            + ((tid < HH) ? wxp[tid] * x[b * HH + tid] : 0.0f);
    red[tid] = p;
    __syncthreads();
#pragma unroll
    for (int o = 256; o > 0; o >>= 1) {
        if (tid < o) red[tid] += red[tid + o];
        __syncthreads();
    }
    if (tid == 0)
        dout[OFF_PG + (size_t)b * TT + t] = 1.0f / (1.0f + expf(-(red[0] + bxp[0])));
}

// ---------------- row softmax over V (in place in d_out), grid 2048 ----------------
__global__ __launch_bounds__(256) void k_vsoftmax(float* __restrict__ out)
{
    const int r = blockIdx.x, tid = threadIdx.x;
    float* row = out + (size_t)r * VV;
    float m = -INFINITY, s = 0.0f;
    for (int v = tid; v < VV; v += 256) {
        float l = row[v];
        if (l > m) { s = s * expf(m - l) + 1.0f; m = l; }
        else       { s += expf(l - m); }
    }
    __shared__ float sm[256], ss[256];
    sm[tid] = m; ss[tid] = s;
    __syncthreads();
#pragma unroll
    for (int o = 128; o > 0; o >>= 1) {
        if (tid < o) {
            float m2 = fmaxf(sm[tid], sm[tid + o]);
            ss[tid] = ss[tid] * expf(sm[tid] - m2) + ss[tid + o] * expf(sm[tid + o] - m2);
            sm[tid] = m2;
        }
        __syncthreads();
    }
    float M = sm[0], inv = 1.0f / ss[0];
    for (int v = tid; v < VV; v += 256)
        row[v] = expf(row[v] - M) * inv;
}

// ---------------- final h,c copy ----------------
__global__ void k_final(const float* __restrict__ h, const float* __restrict__ c,
                        float* __restrict__ out)
{
    int i = blockIdx.x * 256 + threadIdx.x;
    if (i < BB * HH) {
        out[OFF_H + i] = h[i];
        out[OFF_C + i] = c[i];
    }
}

// ---------------- host ----------------
extern "C" void kernel_launch(void* const* d_in, const int* in_sizes, int n_in,
                              void* d_out, int out_size)
{
    const int*   ids  = (const int*)d_in[0];
    const float* h0   = (const float*)d_in[1];
    const float* c0   = (const float*)d_in[2];
    const float* enc  = (const float*)d_in[3];
    const unsigned char* mask = (const unsigned char*)d_in[4];
    const float* emb  = (const float*)d_in[5];
    const float* Wr   = (const float*)d_in[6];
    const float* br   = (const float*)d_in[7];
    const float* Wih  = (const float*)d_in[8];
    const float* Whh  = (const float*)d_in[9];
    const float* bih  = (const float*)d_in[10];
    const float* bhh  = (const float*)d_in[11];
    const float* Wh_a = (const float*)d_in[12];
    const float* Ws_a = (const float*)d_in[13];
    const float* bs_a = (const float*)d_in[14];
    const float* v_a  = (const float*)d_in[15];
    const float* wh_p = (const float*)d_in[16];
    const float* ws_p = (const float*)d_in[17];
    const float* wx_p = (const float*)d_in[18];
    const float* bx_p = (const float*)d_in[19];
    const float* Wvr  = (const float*)d_in[20];
    const float* bvr  = (const float*)d_in[21];
    const float* Wvo  = (const float*)d_in[22];
    const float* bvo  = (const float*)d_in[23];
    float* out = (float*)d_out;

    float *encf, *hbuf, *cbuf, *ctx, *xp, *decp, *scoresp, *vredp;
    cudaGetSymbolAddress((void**)&encf,    g_enc_feat);
    cudaGetSymbolAddress((void**)&hbuf,    g_hbuf);
    cudaGetSymbolAddress((void**)&cbuf,    g_cbuf);
    cudaGetSymbolAddress((void**)&ctx,     g_ctx);
    cudaGetSymbolAddress((void**)&xp,      g_x);
    cudaGetSymbolAddress((void**)&decp,    g_dec);
    cudaGetSymbolAddress((void**)&scoresp, g_scores);
    cudaGetSymbolAddress((void**)&vredp,   g_vred);
    float* hA = hbuf;            float* hB = hbuf + BB * HH;
    float* cA = cbuf;            float* cB = cbuf + BB * HH;

    k_init<<<64, 256>>>(h0, c0, hA, cA, ctx);

    // enc_feat[b,s,h] = enc[b,s,:] . Wh_a[h,:]   (loop-invariant, hoisted)
    sgemm_abt<<<dim3(2, 100), 256>>>(enc, Wh_a, nullptr, encf, BB * SS, HH, H2);

    for (int t = 0; t < TT; t++) {
        const float* hi = (t & 1) ? hB : hA;
        const float* ci = (t & 1) ? cB : cA;
        float* ho = (t & 1) ? hA : hB;
        float* co = (t & 1) ? cA : cB;

        k_x<<<32, 256>>>(ids, emb, ctx, Wr, br, xp, t);
        k_gates<<<32, 256>>>(xp, hi, ci, Wih, Whh, bih, bhh, ho, co);
        k_rowlin<<<32, 256>>>(ho, HH, co, HH, Ws_a, 512, bs_a, decp, HH);
        k_scores<<<dim3(50, 32), 256>>>(encf, decp, v_a, mask, scoresp);
        k_attn_ctx<<<32, 512>>>(scoresp, enc, ho, co, xp,
                                wh_p, ws_p, wx_p, bx_p, ctx, out, t);
        k_rowlin<<<32, 256>>>(ho, HH, ctx, H2, Wvr, 768, bvr,
                              vredp + t * HH, TT * HH);
    }

    // batched vocab projection for ALL (b,t): logits -> d_out vocab region
    sgemm_abt<<<dim3(391, 16), 256>>>(vredp, Wvo, bvo, out, BB * TT, VV, HH);
    k_vsoftmax<<<BB * TT, 256>>>(out);

    // t=63 wrote buffer A
    k_final<<<32, 256>>>(hA, cA, out);
}

// round 5
// speedup vs baseline: 2.3889x; 2.3889x over previous
#include <cuda_runtime.h>
#include <cuda_bf16.h>
#include <math.h>

#define BB 32
#define TT 64
#define SS 400
#define HH 256
#define EE 128
#define VV 50000
#define H2 512

#define NB  148
#define TPB 512

// d_out layout (fp32): vocab_dists[B,T,V], attn[B,T,S], pgen[B,T,1], h[B,H], c[B,H]
#define OFF_ATTN 102400000ull
#define OFF_PG   103219200ull
#define OFF_H    103221248ull
#define OFF_C    103229440ull

// ---------------- scratch ----------------
__device__ unsigned g_cnt;
__device__ float g_Wf[1024 * 640];      // Wih @ Wr  [4H, 640]
__device__ float g_bf[1024];            // bih + bhh + Wih @ br
__device__ float g_wxr[641];            // Wr^T @ wx_p (640) ; [640] = wx_p.br + bx_p
__device__ float g_enc_feat[BB * SS * HH];
__device__ float g_h[2][BB * HH];
__device__ float g_c[2][BB * HH];
__device__ float g_ctx[BB * H2];
__device__ float g_dec[BB * HH];
__device__ float g_scores[BB * SS];
__device__ float g_vred[BB * TT * HH];  // rows r = b*T+t

__device__ __forceinline__ float sigf(float v) { return 1.0f / (1.0f + expf(-v)); }
__device__ __forceinline__ float ftanh(float x) {
    float r; asm("tanh.approx.f32 %0, %1;" : "=f"(r) : "f"(x)); return r;
}
#define NEG_INF __int_as_float(0xff800000)

// ---------------- grid-wide software barrier (all NB blocks resident) ----------------
__device__ __forceinline__ void gbarrier(unsigned& target) {
    __syncthreads();
    if (threadIdx.x == 0) {
        unsigned* pc = &g_cnt;
        asm volatile("red.release.gpu.global.add.u32 [%0], 1;" :: "l"(pc) : "memory");
        target += NB;
        unsigned v;
        asm volatile("ld.acquire.gpu.global.u32 %0, [%1];" : "=r"(v) : "l"(pc) : "memory");
        while (v < target) {
            asm volatile("nanosleep.u32 128;");
            asm volatile("ld.acquire.gpu.global.u32 %0, [%1];" : "=r"(v) : "l"(pc) : "memory");
        }
    }
    __syncthreads();
}

// ---------------- prep: reset barrier, bf, wxr ----------------
__global__ void k_prep(const float* __restrict__ Wih, const float* __restrict__ br,
                       const float* __restrict__ bih, const float* __restrict__ bhh,
                       const float* __restrict__ Wr, const float* __restrict__ wxp,
                       const float* __restrict__ bxp) {
    int p = blockIdx.x, tid = threadIdx.x;
    if (p == 0 && tid == 0) g_cnt = 0;
    if (p < 4) {
        int n = p * 256 + tid;
        float acc = bih[n] + bhh[n];
        const float* w = Wih + (size_t)n * 256;
        for (int m = 0; m < 256; m++) acc += w[m] * br[m];
        g_bf[n] = acc;
    } else if (p < 7) {
        int k = (p - 4) * 256 + tid;
        if (k < 640) {
            float acc = 0.f;
            for (int m = 0; m < 256; m++) acc += wxp[m] * Wr[(size_t)m * 640 + k];
            g_wxr[k] = acc;
        }
    } else if (tid == 0) {
        float acc = bxp[0];
        for (int m = 0; m < 256; m++) acc += wxp[m] * br[m];
        g_wxr[640] = acc;
    }
}

__global__ void k_init(const float* __restrict__ h0, const float* __restrict__ c0) {
    int i = blockIdx.x * 256 + threadIdx.x;
    if (i < BB * HH) { g_h[0][i] = h0[i]; g_c[0][i] = c0[i]; }
    if (i < BB * H2) g_ctx[i] = 0.0f;
}

// ---------------- GEMM: C[M,N] = A[M,K] @ Bw[N,K]^T + bias ----------------
__global__ __launch_bounds__(256) void sgemm_abt(
    const float* __restrict__ A, const float* __restrict__ Bw,
    const float* __restrict__ bias, float* __restrict__ C,
    int M, int N, int K)
{
    __shared__ float As[8][128];
    __shared__ float Bs[8][128];
    const int tid = threadIdx.x;
    const int row0 = blockIdx.y << 7;
    const int col0 = blockIdx.x << 7;
    const int tr = (tid >> 4) << 3;
    const int tc = (tid & 15) << 3;
    float acc[8][8];
#pragma unroll
    for (int i = 0; i < 8; i++)
#pragma unroll
        for (int j = 0; j < 8; j++) acc[i][j] = 0.0f;
    const int lr = tid >> 1, lk = (tid & 1) << 2;
    const bool bok = (col0 + lr) < N;
    for (int k0 = 0; k0 < K; k0 += 8) {
        float4 av = *(const float4*)&A[(size_t)(row0 + lr) * K + k0 + lk];
        float4 bv = bok ? *(const float4*)&Bw[(size_t)(col0 + lr) * K + k0 + lk]
                        : make_float4(0.f, 0.f, 0.f, 0.f);
        As[lk + 0][lr] = av.x; As[lk + 1][lr] = av.y; As[lk + 2][lr] = av.z; As[lk + 3][lr] = av.w;
        Bs[lk + 0][lr] = bv.x; Bs[lk + 1][lr] = bv.y; Bs[lk + 2][lr] = bv.z; Bs[lk + 3][lr] = bv.w;
        __syncthreads();
#pragma unroll
        for (int kk = 0; kk < 8; kk++) {
            float4 a0 = *(const float4*)&As[kk][tr];
            float4 a1 = *(const float4*)&As[kk][tr + 4];
            float4 b0 = *(const float4*)&Bs[kk][tc];
            float4 b1 = *(const float4*)&Bs[kk][tc + 4];
            float a[8] = {a0.x, a0.y, a0.z, a0.w, a1.x, a1.y, a1.z, a1.w};
            float b[8] = {b0.x, b0.y, b0.z, b0.w, b1.x, b1.y, b1.z, b1.w};
#pragma unroll
            for (int i = 0; i < 8; i++)
#pragma unroll
                for (int j = 0; j < 8; j++) acc[i][j] += a[i] * b[j];
        }
        __syncthreads();
    }
#pragma unroll
    for (int i = 0; i < 8; i++) {
        size_t r = row0 + tr + i;
#pragma unroll
        for (int j = 0; j < 8; j++) {
            int c = col0 + tc + j;
            if (c < N) C[r * (size_t)N + c] = acc[i][j] + (bias ? bias[c] : 0.0f);
        }
    }
}

// ---------------- GEMM (B not transposed): C[M,N] = A[M,K] @ Bn[K,N]. N%128==0 ----------------
__global__ __launch_bounds__(256) void sgemm_abn(
    const float* __restrict__ A, const float* __restrict__ Bn,
    float* __restrict__ C, int M, int N, int K)
{
    __shared__ float As[8][128];
    __shared__ float Bs[8][128];
    const int tid = threadIdx.x;
    const int row0 = blockIdx.y << 7;
    const int col0 = blockIdx.x << 7;
    const int tr = (tid >> 4) << 3;
    const int tc = (tid & 15) << 3;
    float acc[8][8];
#pragma unroll
    for (int i = 0; i < 8; i++)
#pragma unroll
        for (int j = 0; j < 8; j++) acc[i][j] = 0.0f;
    const int lr = tid >> 1, lk = (tid & 1) << 2;
    const int blc = (tid & 31) << 2, blk = tid >> 5;
    for (int k0 = 0; k0 < K; k0 += 8) {
        float4 av = *(const float4*)&A[(size_t)(row0 + lr) * K + k0 + lk];
        As[lk + 0][lr] = av.x; As[lk + 1][lr] = av.y; As[lk + 2][lr] = av.z; As[lk + 3][lr] = av.w;
        float4 bv = *(const float4*)&Bn[(size_t)(k0 + blk) * N + col0 + blc];
        Bs[blk][blc + 0] = bv.x; Bs[blk][blc + 1] = bv.y; Bs[blk][blc + 2] = bv.z; Bs[blk][blc + 3] = bv.w;
        __syncthreads();
#pragma unroll
        for (int kk = 0; kk < 8; kk++) {
            float4 a0 = *(const float4*)&As[kk][tr];
            float4 a1 = *(const float4*)&As[kk][tr + 4];
            float4 b0 = *(const float4*)&Bs[kk][tc];
            float4 b1 = *(const float4*)&Bs[kk][tc + 4];
            float a[8] = {a0.x, a0.y, a0.z, a0.w, a1.x, a1.y, a1.z, a1.w};
            float b[8] = {b0.x, b0.y, b0.z, b0.w, b1.x, b1.y, b1.z, b1.w};
#pragma unroll
            for (int i = 0; i < 8; i++)
#pragma unroll
                for (int j = 0; j < 8; j++) acc[i][j] += a[i] * b[j];
        }
        __syncthreads();
    }
#pragma unroll
    for (int i = 0; i < 8; i++) {
        size_t r = row0 + tr + i;
#pragma unroll
        for (int j = 0; j < 8; j++)
            C[r * (size_t)N + col0 + tc + j] = acc[i][j];
    }
}

// ================= persistent recurrence kernel =================
// Roles in staged small GEMMs: b = tid&31 (lane), jl = (tid>>5)&1, kq = tid>>6 (0..7).
// Weight loads are warp-uniform (broadcast); smem pitch 132 is conflict-free for LDS.128.

struct Smem {
    float sA[32 * 132];      // staged activations [b][k] pitch 132
    float sred[64 * 36];     // K-split partials
    float sat[SS];           // attention weights
    float red[512];          // reductions
    float spart[4 * 128];    // ctx partials
    float spg[512];          // pgen partials
};

__device__ __forceinline__ void stage_chunk_gates(
    Smem* sm, int t, int cch, const int* __restrict__ ids,
    const float* __restrict__ emb, const float* __restrict__ hin)
{
    const int tid = threadIdx.x;
#pragma unroll
    for (int r = 0; r < 8; r++) {
        int i = tid + r * 512;
        int bb = i >> 7, kk = i & 127;
        int kg = cch * 128 + kk;
        float v;
        if (kg < 128)      v = emb[(size_t)ids[bb * TT + t] * EE + kg];
        else if (kg < 640) v = g_ctx[bb * H2 + kg - 128];
        else               v = hin[bb * HH + kg - 640];
        sm->sA[bb * 132 + kk] = v;
    }
}

__device__ __forceinline__ void stage_chunk_2(
    Smem* sm, int cch, const float* __restrict__ s0, const float* __restrict__ s1)
{   // K laid out as [s0(256) | s1(...)], chunk cch of 128
    const int tid = threadIdx.x;
#pragma unroll
    for (int r = 0; r < 8; r++) {
        int i = tid + r * 512;
        int bb = i >> 7, kk = i & 127;
        int kg = cch * 128 + kk;
        float v = (kg < 256) ? s0[bb * HH + kg] : s1[bb * H2 + kg - 256];
        sm->sA[bb * 132 + kk] = v;
    }
}

__device__ __forceinline__ float dot16(const float* __restrict__ a, const float* __restrict__ w) {
    float4 a0 = *(const float4*)(a + 0), a1 = *(const float4*)(a + 4);
    float4 a2 = *(const float4*)(a + 8), a3 = *(const float4*)(a + 12);
    float4 w0 = *(const float4*)(w + 0), w1 = *(const float4*)(w + 4);
    float4 w2 = *(const float4*)(w + 8), w3 = *(const float4*)(w + 12);
    float s0 = a0.x * w0.x + a0.y * w0.y + a0.z * w0.z + a0.w * w0.w;
    float s1 = a1.x * w1.x + a1.y * w1.y + a1.z * w1.z + a1.w * w1.w;
    float s2 = a2.x * w2.x + a2.y * w2.y + a2.z * w2.z + a2.w * w2.w;
    float s3 = a3.x * w3.x + a3.y * w3.y + a3.z * w3.z + a3.w * w3.w;
    return (s0 + s1) + (s2 + s3);
}

// vred(tp) = [h_new(tp) | ctx(tp)] @ Wvr^T + bvr   (K=768, 6 chunks)
__device__ __forceinline__ void vred_block(
    Smem* sm, int tp, const float* __restrict__ hprev,
    const float* __restrict__ Wvr, const float* __restrict__ bvr, int p)
{
    const int tid = threadIdx.x;
    const int b = tid & 31, jl = (tid >> 5) & 1, kq = tid >> 6;
    const int j = p * 2 + jl;
    float acc = 0.f;
    for (int cch = 0; cch < 6; cch++) {
        __syncthreads();
        stage_chunk_2(sm, cch, hprev, g_ctx);
        __syncthreads();
        int kg = cch * 128 + kq * 16;
        acc += dot16(&sm->sA[b * 132 + kq * 16], &Wvr[(size_t)j * 768 + kg]);
    }
    __syncthreads();
    sm->sred[(jl * 32 + b) * 36 + kq] = acc;
    __syncthreads();
    if (tid < 64) {
        int bb = tid & 31, jjl = tid >> 5, jj = p * 2 + jjl;
        const float* r = &sm->sred[(jjl * 32 + bb) * 36];
        float s = ((r[0] + r[1]) + (r[2] + r[3])) + ((r[4] + r[5]) + (r[6] + r[7]));
        g_vred[((size_t)bb * TT + tp) * HH + jj] = s + bvr[jj];
    }
    __syncthreads();
}

// gates(t) + LSTM pointwise -> hout, cout  (K=896, 7 chunks; chunks 0-4 Wf, 5-6 Whh)
__device__ __forceinline__ void gates_block(
    Smem* sm, int t, const int* __restrict__ ids, const float* __restrict__ emb,
    const float* __restrict__ hin, const float* __restrict__ cin,
    const float* __restrict__ Whh, float* __restrict__ hout, float* __restrict__ cout, int p)
{
    const int tid = threadIdx.x;
    const int b = tid & 31, jl = (tid >> 5) & 1, kq = tid >> 6;
    const int j = p * 2 + jl;
    float a0 = 0.f, a1 = 0.f, a2 = 0.f, a3 = 0.f;
    for (int cch = 0; cch < 7; cch++) {
        __syncthreads();
        stage_chunk_gates(sm, t, cch, ids, emb, hin);
        __syncthreads();
        const float* av = &sm->sA[b * 132 + kq * 16];
        int kg = cch * 128 + kq * 16;
        if (cch < 5) {
            a0 += dot16(av, &g_Wf[(size_t)(0 * 256 + j) * 640 + kg]);
            a1 += dot16(av, &g_Wf[(size_t)(1 * 256 + j) * 640 + kg]);
            a2 += dot16(av, &g_Wf[(size_t)(2 * 256 + j) * 640 + kg]);
            a3 += dot16(av, &g_Wf[(size_t)(3 * 256 + j) * 640 + kg]);
        } else {
            int kh = kg - 640;
            a0 += dot16(av, &Whh[(size_t)(0 * 256 + j) * 256 + kh]);
            a1 += dot16(av, &Whh[(size_t)(1 * 256 + j) * 256 + kh]);
            a2 += dot16(av, &Whh[(size_t)(2 * 256 + j) * 256 + kh]);
            a3 += dot16(av, &Whh[(size_t)(3 * 256 + j) * 256 + kh]);
        }
    }
    __syncthreads();
    float* r = &sm->sred[(jl * 32 + b) * 36 + kq * 4];
    r[0] = a0; r[1] = a1; r[2] = a2; r[3] = a3;
    __syncthreads();
    if (tid < 64) {
        int bb = tid & 31, jjl = tid >> 5, jj = p * 2 + jjl;
        const float* rr = &sm->sred[(jjl * 32 + bb) * 36];
        float s0 = 0.f, s1 = 0.f, s2 = 0.f, s3 = 0.f;
#pragma unroll
        for (int q = 0; q < 8; q++) {
            s0 += rr[q * 4 + 0]; s1 += rr[q * 4 + 1];
            s2 += rr[q * 4 + 2]; s3 += rr[q * 4 + 3];
        }
        float gi = s0 + g_bf[jj];
        float gf = s1 + g_bf[256 + jj];
        float gg = s2 + g_bf[512 + jj];
        float go = s3 + g_bf[768 + jj];
        float co = cin[bb * HH + jj];
        float cn = sigf(gf) * co + sigf(gi) * tanhf(gg);
        float hn = sigf(go) * tanhf(cn);
        cout[bb * HH + jj] = cn;
        hout[bb * HH + jj] = hn;
    }
    __syncthreads();
}

// dec = [h_new | c_new] @ Ws_a^T + bs_a  (K=512, 4 chunks)
__device__ __forceinline__ void dec_block(
    Smem* sm, const float* __restrict__ hn, const float* __restrict__ cn,
    const float* __restrict__ Wsa, const float* __restrict__ bsa, int p)
{
    const int tid = threadIdx.x;
    const int b = tid & 31, jl = (tid >> 5) & 1, kq = tid >> 6;
    const int j = p * 2 + jl;
    float acc = 0.f;
    for (int cch = 0; cch < 4; cch++) {
        __syncthreads();
        {
            const int t2 = threadIdx.x;
#pragma unroll
            for (int r = 0; r < 8; r++) {
                int i = t2 + r * 512;
                int bb = i >> 7, kk = i & 127;
                int kg = cch * 128 + kk;
                sm->sA[bb * 132 + kk] = (kg < 256) ? hn[bb * HH + kg] : cn[bb * HH + kg - 256];
            }
        }
        __syncthreads();
        int kg = cch * 128 + kq * 16;
        acc += dot16(&sm->sA[b * 132 + kq * 16], &Wsa[(size_t)j * 512 + kg]);
    }
    __syncthreads();
    sm->sred[(jl * 32 + b) * 36 + kq] = acc;
    __syncthreads();
    if (tid < 64) {
        int bb = tid & 31, jjl = tid >> 5, jj = p * 2 + jjl;
        const float* r = &sm->sred[(jjl * 32 + bb) * 36];
        float s = ((r[0] + r[1]) + (r[2] + r[3])) + ((r[4] + r[5]) + (r[6] + r[7]));
        g_dec[bb * HH + jj] = s + bsa[jj];
    }
    __syncthreads();
}

// pgen(tp): blocks 128..143, 2 b per block
__device__ __forceinline__ void pgen_block(
    Smem* sm, int tp, const int* __restrict__ ids, const float* __restrict__ emb,
    const float* __restrict__ hn, const float* __restrict__ cn,
    const float* __restrict__ whp, const float* __restrict__ wsp,
    float* __restrict__ dout, int p)
{
    const int tid = threadIdx.x;
    const int half = tid >> 8, lt = tid & 255;
    const int b = (p - 128) * 2 + half;
    float acc = 0.f;
    for (int k = lt; k < 512; k += 256) {
        float sv = (k < 256) ? hn[b * HH + k] : cn[b * HH + k - 256];
        acc += whp[k] * g_ctx[b * H2 + k] + wsp[k] * sv;
    }
    int id = ids[b * TT + tp];
    for (int k = lt; k < 640; k += 256) {
        float av = (k < 128) ? emb[(size_t)id * EE + k] : g_ctx[b * H2 + k - 128];
        acc += g_wxr[k] * av;
    }
    sm->spg[tid] = acc;
    __syncthreads();
#pragma unroll
    for (int o = 128; o > 0; o >>= 1) {
        if (lt < o) sm->spg[half * 256 + lt] += sm->spg[half * 256 + lt + o];
        __syncthreads();
    }
    if (lt == 0)
        dout[OFF_PG + (size_t)b * TT + tp] = sigf(sm->spg[half * 256] + g_wxr[640]);
    __syncthreads();
}

__global__ __launch_bounds__(TPB, 1) void k_persistent(
    const int* __restrict__ ids, const float* __restrict__ emb,
    const float* __restrict__ enc, const unsigned char* __restrict__ mask,
    const float* __restrict__ Whh, const float* __restrict__ Wsa,
    const float* __restrict__ bsa, const float* __restrict__ va,
    const float* __restrict__ whp, const float* __restrict__ wsp,
    const float* __restrict__ Wvr, const float* __restrict__ bvr,
    float* __restrict__ dout)
{
    __shared__ Smem sm;
    const int p = blockIdx.x, tid = threadIdx.x;
    unsigned target = 0;

    for (int t = 0; t < TT; t++) {
        const float* hin = g_h[t & 1];
        const float* cin = g_c[t & 1];
        float* hout = g_h[(t + 1) & 1];
        float* cout = g_c[(t + 1) & 1];

        // ---- P1: vred(t-1) + pgen(t-1) + gates(t) ----
        if (p < 128) {
            if (t > 0) vred_block(&sm, t - 1, hin, Wvr, bvr, p);
            gates_block(&sm, t, ids, emb, hin, cin, Whh, hout, cout, p);
        } else if (p < 144) {
            if (t > 0) pgen_block(&sm, t - 1, ids, emb, hin, cin, whp, wsp, dout, p);
        }
        gbarrier(target);

        // ---- P2: dec_feat ----
        if (p < 128) dec_block(&sm, hout, cout, Wsa, bsa, p);
        gbarrier(target);

        // ---- P3: scores ----
        {
            const int w = tid >> 5, lane = tid & 31;
#pragma unroll
            for (int i = 0; i < 6; i++) {
                int u = p * 16 + w + i * (NB * 16);
                if (u < BB * SS) {
                    int b = u / SS;
                    const float4* ef = (const float4*)(g_enc_feat + (size_t)u * HH);
                    const float4* dp = (const float4*)(g_dec + b * HH);
                    const float4* vp = (const float4*)va;
                    float acc = 0.f;
#pragma unroll
                    for (int h = 0; h < 2; h++) {
                        int ix = lane + h * 32;
                        float4 e = ef[ix], d = dp[ix], v = vp[ix];
                        acc += v.x * ftanh(e.x + d.x) + v.y * ftanh(e.y + d.y)
                             + v.z * ftanh(e.z + d.z) + v.w * ftanh(e.w + d.w);
                    }
#pragma unroll
                    for (int o = 16; o > 0; o >>= 1) acc += __shfl_xor_sync(0xffffffffu, acc, o);
                    if (lane == 0) g_scores[u] = mask[u] ? NEG_INF : acc;
                }
            }
        }
        gbarrier(target);

        // ---- P4: softmax + ctx ----
        if (p < 128) {
            const int b = p >> 2, ch = p & 3;
            float sc = (tid < SS) ? g_scores[b * SS + tid] : NEG_INF;
            sm.red[tid] = sc;
            __syncthreads();
#pragma unroll
            for (int o = 256; o > 0; o >>= 1) {
                if (tid < o) sm.red[tid] = fmaxf(sm.red[tid], sm.red[tid + o]);
                __syncthreads();
            }
            float m = sm.red[0];
            __syncthreads();
            float e = (tid < SS) ? expf(sc - m) : 0.f;
            sm.red[tid] = e;
            __syncthreads();
#pragma unroll
            for (int o = 256; o > 0; o >>= 1) {
                if (tid < o) sm.red[tid] += sm.red[tid + o];
                __syncthreads();
            }
            float inv = 1.0f / sm.red[0];
            __syncthreads();
            if (tid < SS) {
                float a = e * inv;
                sm.sat[tid] = a;
                if (ch == 0) dout[OFF_ATTN + ((size_t)b * TT + t) * SS + tid] = a;
            }
            __syncthreads();
            const int d = tid & 127, sg = tid >> 7;
            const float* ep = enc + ((size_t)b * SS + sg * 100) * H2 + ch * 128 + d;
            float acc = 0.f;
#pragma unroll 4
            for (int s = 0; s < 100; s++) acc += sm.sat[sg * 100 + s] * ep[(size_t)s * H2];
            sm.spart[sg * 128 + d] = acc;
            __syncthreads();
            if (tid < 128) {
                float v = (sm.spart[tid] + sm.spart[128 + tid])
                        + (sm.spart[256 + tid] + sm.spart[384 + tid]);
                g_ctx[b * H2 + ch * 128 + tid] = v;
            }
        }
        gbarrier(target);
    }

    // ---- tail: vred(63), pgen(63), final h/c ----
    const float* hf = g_h[0];
    const float* cf = g_c[0];
    if (p < 128) {
        vred_block(&sm, TT - 1, hf, Wvr, bvr, p);
    } else if (p < 144) {
        pgen_block(&sm, TT - 1, ids, emb, hf, cf, whp, wsp, dout, p);
    } else {
        for (int i0 = (p - 144) * 2048 + tid; i0 < (p - 143) * 2048; i0 += TPB) {
            dout[OFF_H + i0] = hf[i0];
            dout[OFF_C + i0] = cf[i0];
        }
    }
}

// ---------------- row softmax over V (in place in d_out), grid 2048 ----------------
__global__ __launch_bounds__(256) void k_vsoftmax(float* __restrict__ out)
{
    const int r = blockIdx.x, tid = threadIdx.x;
    float* row = out + (size_t)r * VV;
    float m = NEG_INF, s = 0.0f;
    for (int v = tid; v < VV; v += 256) {
        float l = row[v];
        if (l > m) { s = s * expf(m - l) + 1.0f; m = l; }
        else       { s += expf(l - m); }
    }
    __shared__ float sm[256], ss[256];
    sm[tid] = m; ss[tid] = s;
    __syncthreads();
#pragma unroll
    for (int o = 128; o > 0; o >>= 1) {
        if (tid < o) {
            float m2 = fmaxf(sm[tid], sm[tid + o]);
            ss[tid] = ss[tid] * expf(sm[tid] - m2) + ss[tid + o] * expf(sm[tid + o] - m2);
            sm[tid] = m2;
        }
        __syncthreads();
    }
    float M = sm[0], inv = 1.0f / ss[0];
    for (int v = tid; v < VV; v += 256)
        row[v] = expf(row[v] - M) * inv;
}

// ---------------- host ----------------
extern "C" void kernel_launch(void* const* d_in, const int* in_sizes, int n_in,
                              void* d_out, int out_size)
{
    const int*   ids  = (const int*)d_in[0];
    const float* h0   = (const float*)d_in[1];
    const float* c0   = (const float*)d_in[2];
    const float* enc  = (const float*)d_in[3];
    const unsigned char* mask = (const unsigned char*)d_in[4];
    const float* emb  = (const float*)d_in[5];
    const float* Wr   = (const float*)d_in[6];
    const float* br   = (const float*)d_in[7];
    const float* Wih  = (const float*)d_in[8];
    const float* Whh  = (const float*)d_in[9];
    const float* bih  = (const float*)d_in[10];
    const float* bhh  = (const float*)d_in[11];
    const float* Wh_a = (const float*)d_in[12];
    const float* Ws_a = (const float*)d_in[13];
    const float* bs_a = (const float*)d_in[14];
    const float* v_a  = (const float*)d_in[15];
    const float* wh_p = (const float*)d_in[16];
    const float* ws_p = (const float*)d_in[17];
    const float* wx_p = (const float*)d_in[18];
    const float* bx_p = (const float*)d_in[19];
    const float* Wvr  = (const float*)d_in[20];
    const float* bvr  = (const float*)d_in[21];
    const float* Wvo  = (const float*)d_in[22];
    const float* bvo  = (const float*)d_in[23];
    float* out = (float*)d_out;

    float *encf, *vredp, *Wfp;
    cudaGetSymbolAddress((void**)&encf,  g_enc_feat);
    cudaGetSymbolAddress((void**)&vredp, g_vred);
    cudaGetSymbolAddress((void**)&Wfp,   g_Wf);

    // prep: barrier reset, fused biases, folded pgen vector, h/c/ctx init
    k_prep<<<8, 256>>>(Wih, br, bih, bhh, Wr, wx_p, bx_p);
    k_init<<<64, 256>>>(h0, c0);

    // Wf = Wih[1024,256] @ Wr[256,640]
    sgemm_abn<<<dim3(5, 8), 256>>>(Wih, Wr, Wfp, 1024, 640, 256);

    // enc_feat = enc @ Wh_a^T (loop-invariant)
    sgemm_abt<<<dim3(2, 100), 256>>>(enc, Wh_a, nullptr, encf, BB * SS, HH, H2);

    // full 64-step recurrence in one persistent kernel
    k_persistent<<<NB, TPB>>>(ids, emb, enc, mask, Whh, Ws_a, bs_a, v_a,
                              wh_p, ws_p, Wvr, bvr, out);

    // batched vocab projection + softmax
    sgemm_abt<<<dim3(391, 16), 256>>>(vredp, Wvo, bvo, out, BB * TT, VV, HH);
    k_vsoftmax<<<BB * TT, 256>>>(out);
}

// round 7
// speedup vs baseline: 3.3656x; 1.4089x over previous
#include <cuda_runtime.h>
#include <cuda_bf16.h>
#include <math.h>
#include <cstdint>

#define BB 32
#define TT 64
#define SS 400
#define HH 256
#define EE 128
#define VV 50000
#define H2 512

#define NB  148
#define TPB 512

// d_out layout (fp32): vocab_dists[B,T,V], attn[B,T,S], pgen[B,T,1], h[B,H], c[B,H]
#define OFF_ATTN 102400000ull
#define OFF_PG   103219200ull
#define OFF_H    103221248ull
#define OFF_C    103229440ull

// ---------------- scratch ----------------
__device__ unsigned g_cnt;
__device__ float g_Wf[1024 * 640];      // Wih @ Wr  [4H, 640]
__device__ float g_bf[1024];            // bih + bhh + Wih @ br
__device__ float g_wxr[641];            // Wr^T @ wx_p (640) ; [640] = wx_p.br + bx_p
__device__ float g_enc_feat[BB * SS * HH];
__device__ float g_h[2][BB * HH];
__device__ float g_c[2][BB * HH];
__device__ float g_ctx[BB * H2];
__device__ float g_dec[BB * HH];
__device__ float g_scores[BB * SS];
__device__ float g_vred[BB * TT * HH];          // rows r = b*T+t
__device__ __nv_bfloat16 g_vred_bf[BB * TT * HH];
__device__ __nv_bfloat16 g_Wvo_bf[VV * HH];

__device__ __forceinline__ float sigf(float v) { return 1.0f / (1.0f + expf(-v)); }
__device__ __forceinline__ float ftanh(float x) {
    float r; asm("tanh.approx.f32 %0, %1;" : "=f"(r) : "f"(x)); return r;
}
#define NEG_INF __int_as_float(0xff800000)

// ---------------- grid-wide software barrier (all NB blocks resident) ----------------
__device__ __forceinline__ void gbarrier(unsigned& target) {
    __syncthreads();
    if (threadIdx.x == 0) {
        unsigned* pc = &g_cnt;
        asm volatile("red.release.gpu.global.add.u32 [%0], 1;" :: "l"(pc) : "memory");
        target += NB;
        unsigned v;
        asm volatile("ld.acquire.gpu.global.u32 %0, [%1];" : "=r"(v) : "l"(pc) : "memory");
        while (v < target) {
            asm volatile("nanosleep.u32 128;");
            asm volatile("ld.acquire.gpu.global.u32 %0, [%1];" : "=r"(v) : "l"(pc) : "memory");
        }
    }
    __syncthreads();
}

// ---------------- prep: reset barrier, bf, wxr ----------------
__global__ void k_prep(const float* __restrict__ Wih, const float* __restrict__ br,
                       const float* __restrict__ bih, const float* __restrict__ bhh,
                       const float* __restrict__ Wr, const float* __restrict__ wxp,
                       const float* __restrict__ bxp) {
    int p = blockIdx.x, tid = threadIdx.x;
    if (p == 0 && tid == 0) g_cnt = 0;
    if (p < 4) {
        int n = p * 256 + tid;
        float acc = bih[n] + bhh[n];
        const float* w = Wih + (size_t)n * 256;
        for (int m = 0; m < 256; m++) acc += w[m] * br[m];
        g_bf[n] = acc;
    } else if (p < 7) {
        int k = (p - 4) * 256 + tid;
        if (k < 640) {
            float acc = 0.f;
            for (int m = 0; m < 256; m++) acc += wxp[m] * Wr[(size_t)m * 640 + k];
            g_wxr[k] = acc;
        }
    } else if (tid == 0) {
        float acc = bxp[0];
        for (int m = 0; m < 256; m++) acc += wxp[m] * br[m];
        g_wxr[640] = acc;
    }
}

__global__ void k_init(const float* __restrict__ h0, const float* __restrict__ c0) {
    int i = blockIdx.x * 256 + threadIdx.x;
    if (i < BB * HH) { g_h[0][i] = h0[i]; g_c[0][i] = c0[i]; }
    if (i < BB * H2) g_ctx[i] = 0.0f;
}

// ---------------- fp32 -> bf16 convert (n4 = count/4) ----------------
__global__ void k_cvt(const float* __restrict__ in, __nv_bfloat16* __restrict__ out, int n4)
{
    int i = blockIdx.x * 256 + threadIdx.x;
    if (i < n4) {
        float4 v = ((const float4*)in)[i];
        __nv_bfloat162 lo = __floats2bfloat162_rn(v.x, v.y);
        __nv_bfloat162 hi = __floats2bfloat162_rn(v.z, v.w);
        ((__nv_bfloat162*)out)[i * 2 + 0] = lo;
        ((__nv_bfloat162*)out)[i * 2 + 1] = hi;
    }
}

// ---------------- GEMM: C[M,N] = A[M,K] @ Bw[N,K]^T + bias (fp32, small uses) ----------------
__global__ __launch_bounds__(256) void sgemm_abt(
    const float* __restrict__ A, const float* __restrict__ Bw,
    const float* __restrict__ bias, float* __restrict__ C,
    int M, int N, int K)
{
    __shared__ float As[8][128];
    __shared__ float Bs[8][128];
    const int tid = threadIdx.x;
    const int row0 = blockIdx.y << 7;
    const int col0 = blockIdx.x << 7;
    const int tr = (tid >> 4) << 3;
    const int tc = (tid & 15) << 3;
    float acc[8][8];
#pragma unroll
    for (int i = 0; i < 8; i++)
#pragma unroll
        for (int j = 0; j < 8; j++) acc[i][j] = 0.0f;
    const int lr = tid >> 1, lk = (tid & 1) << 2;
    const bool bok = (col0 + lr) < N;
    for (int k0 = 0; k0 < K; k0 += 8) {
        float4 av = *(const float4*)&A[(size_t)(row0 + lr) * K + k0 + lk];
        float4 bv = bok ? *(const float4*)&Bw[(size_t)(col0 + lr) * K + k0 + lk]
                        : make_float4(0.f, 0.f, 0.f, 0.f);
        As[lk + 0][lr] = av.x; As[lk + 1][lr] = av.y; As[lk + 2][lr] = av.z; As[lk + 3][lr] = av.w;
        Bs[lk + 0][lr] = bv.x; Bs[lk + 1][lr] = bv.y; Bs[lk + 2][lr] = bv.z; Bs[lk + 3][lr] = bv.w;
        __syncthreads();
#pragma unroll
        for (int kk = 0; kk < 8; kk++) {
            float4 a0 = *(const float4*)&As[kk][tr];
            float4 a1 = *(const float4*)&As[kk][tr + 4];
            float4 b0 = *(const float4*)&Bs[kk][tc];
            float4 b1 = *(const float4*)&Bs[kk][tc + 4];
            float a[8] = {a0.x, a0.y, a0.z, a0.w, a1.x, a1.y, a1.z, a1.w};
            float b[8] = {b0.x, b0.y, b0.z, b0.w, b1.x, b1.y, b1.z, b1.w};
#pragma unroll
            for (int i = 0; i < 8; i++)
#pragma unroll
                for (int j = 0; j < 8; j++) acc[i][j] += a[i] * b[j];
        }
        __syncthreads();
    }
#pragma unroll
    for (int i = 0; i < 8; i++) {
        size_t r = row0 + tr + i;
#pragma unroll
        for (int j = 0; j < 8; j++) {
            int c = col0 + tc + j;
            if (c < N) C[r * (size_t)N + c] = acc[i][j] + (bias ? bias[c] : 0.0f);
        }
    }
}

// ---------------- GEMM (B not transposed): C[M,N] = A[M,K] @ Bn[K,N]. N%128==0 ----------------
__global__ __launch_bounds__(256) void sgemm_abn(
    const float* __restrict__ A, const float* __restrict__ Bn,
    float* __restrict__ C, int M, int N, int K)
{
    __shared__ float As[8][128];
    __shared__ float Bs[8][128];
    const int tid = threadIdx.x;
    const int row0 = blockIdx.y << 7;
    const int col0 = blockIdx.x << 7;
    const int tr = (tid >> 4) << 3;
    const int tc = (tid & 15) << 3;
    float acc[8][8];
#pragma unroll
    for (int i = 0; i < 8; i++)
#pragma unroll
        for (int j = 0; j < 8; j++) acc[i][j] = 0.0f;
    const int lr = tid >> 1, lk = (tid & 1) << 2;
    const int blc = (tid & 31) << 2, blk = tid >> 5;
    for (int k0 = 0; k0 < K; k0 += 8) {
        float4 av = *(const float4*)&A[(size_t)(row0 + lr) * K + k0 + lk];
        As[lk + 0][lr] = av.x; As[lk + 1][lr] = av.y; As[lk + 2][lr] = av.z; As[lk + 3][lr] = av.w;
        float4 bv = *(const float4*)&Bn[(size_t)(k0 + blk) * N + col0 + blc];
        Bs[blk][blc + 0] = bv.x; Bs[blk][blc + 1] = bv.y; Bs[blk][blc + 2] = bv.z; Bs[blk][blc + 3] = bv.w;
        __syncthreads();
#pragma unroll
        for (int kk = 0; kk < 8; kk++) {
            float4 a0 = *(const float4*)&As[kk][tr];
            float4 a1 = *(const float4*)&As[kk][tr + 4];
            float4 b0 = *(const float4*)&Bs[kk][tc];
            float4 b1 = *(const float4*)&Bs[kk][tc + 4];
            float a[8] = {a0.x, a0.y, a0.z, a0.w, a1.x, a1.y, a1.z, a1.w};
            float b[8] = {b0.x, b0.y, b0.z, b0.w, b1.x, b1.y, b1.z, b1.w};
#pragma unroll
            for (int i = 0; i < 8; i++)
#pragma unroll
                for (int j = 0; j < 8; j++) acc[i][j] += a[i] * b[j];
        }
        __syncthreads();
    }
#pragma unroll
    for (int i = 0; i < 8; i++) {
        size_t r = row0 + tr + i;
#pragma unroll
        for (int j = 0; j < 8; j++)
            C[r * (size_t)N + col0 + tc + j] = acc[i][j];
    }
}

// ================= bf16 tensor-core vocab GEMM =================
// C[2048, 50000] = A[2048,256] @ W[50000,256]^T + bias.  mma.sync m16n8k16.
// Block tile 128x128, 8 warps (2 m x 4 n), warp tile 64x32, BK=64.

__device__ __forceinline__ void ldm_x4(unsigned* r, const void* p) {
    unsigned a = (unsigned)__cvta_generic_to_shared(p);
    asm volatile("ldmatrix.sync.aligned.m8n8.x4.shared.b16 {%0,%1,%2,%3}, [%4];"
        : "=r"(r[0]), "=r"(r[1]), "=r"(r[2]), "=r"(r[3]) : "r"(a));
}
__device__ __forceinline__ void mma16816(float* c, const unsigned* a, unsigned b0, unsigned b1) {
    asm volatile("mma.sync.aligned.m16n8k16.row.col.f32.bf16.bf16.f32 "
        "{%0,%1,%2,%3}, {%4,%5,%6,%7}, {%8,%9}, {%0,%1,%2,%3};"
        : "+f"(c[0]), "+f"(c[1]), "+f"(c[2]), "+f"(c[3])
        : "r"(a[0]), "r"(a[1]), "r"(a[2]), "r"(a[3]), "r"(b0), "r"(b1));
}

__global__ __launch_bounds__(256) void hgemm_vocab(
    const __nv_bfloat16* __restrict__ A,   // [2048, 256]
    const __nv_bfloat16* __restrict__ W,   // [VV, 256]
    const float* __restrict__ bias, float* __restrict__ C)
{
    __shared__ __nv_bfloat16 As[128][72];
    __shared__ __nv_bfloat16 Ws[128][72];
    const int n0 = blockIdx.x << 7;
    const int m0 = blockIdx.y << 7;
    const int tid = threadIdx.x;
    const int warp = tid >> 5, lane = tid & 31;
    const int wm = (warp & 1) << 6;    // 0 or 64
    const int wn = (warp >> 1) << 5;   // 0,32,64,96

    float acc[4][4][4];
#pragma unroll
    for (int i = 0; i < 4; i++)
#pragma unroll
        for (int j = 0; j < 4; j++)
#pragma unroll
            for (int q = 0; q < 4; q++) acc[i][j][q] = 0.f;

    for (int k0 = 0; k0 < 256; k0 += 64) {
#pragma unroll
        for (int r = 0; r < 4; r++) {
            int i = tid + r * 256;
            int row = i >> 3, c = (i & 7) * 8;
            *(uint4*)&As[row][c] = *(const uint4*)&A[(size_t)(m0 + row) * 256 + k0 + c];
            uint4 v = make_uint4(0u, 0u, 0u, 0u);
            if (n0 + row < VV)
                v = *(const uint4*)&W[(size_t)(n0 + row) * 256 + k0 + c];
            *(uint4*)&Ws[row][c] = v;
        }
        __syncthreads();
#pragma unroll
        for (int ks = 0; ks < 64; ks += 16) {
            unsigned af[4][4];
#pragma unroll
            for (int ma = 0; ma < 4; ma++)
                ldm_x4(af[ma], &As[wm + ma * 16 + (lane & 15)][ks + (lane >> 4) * 8]);
            unsigned bfr[2][4];
#pragma unroll
            for (int nb = 0; nb < 2; nb++)
                ldm_x4(bfr[nb], &Ws[wn + nb * 16 + (lane & 15)][ks + (lane >> 4) * 8]);
#pragma unroll
            for (int ma = 0; ma < 4; ma++)
#pragma unroll
                for (int na = 0; na < 4; na++)
                    mma16816(acc[ma][na], af[ma],
                             bfr[na >> 1][na & 1], bfr[na >> 1][2 + (na & 1)]);
        }
        __syncthreads();
    }

    // epilogue: c0,c1 -> (row, col..col+1); c2,c3 -> (row+8, ...)
#pragma unroll
    for (int ma = 0; ma < 4; ma++) {
        int r0 = m0 + wm + ma * 16 + (lane >> 2);
#pragma unroll
        for (int na = 0; na < 4; na++) {
            int c = n0 + wn + na * 8 + (lane & 3) * 2;
            if (c < VV) {
                float b0 = bias[c], b1 = bias[c + 1];
                float2 v0 = make_float2(acc[ma][na][0] + b0, acc[ma][na][1] + b1);
                float2 v1 = make_float2(acc[ma][na][2] + b0, acc[ma][na][3] + b1);
                *(float2*)&C[(size_t)r0 * VV + c] = v0;
                *(float2*)&C[(size_t)(r0 + 8) * VV + c] = v1;
            }
        }
    }
}

// ================= persistent recurrence kernel =================
struct Smem {
    float sA[32 * 132];
    float sred[64 * 36];
    float sat[SS];
    float red[512];
    float spart[4 * 128];
    float spg[512];
};

__device__ __forceinline__ void stage_chunk_gates(
    Smem* sm, int t, int cch, const int* __restrict__ ids,
    const float* __restrict__ emb, const float* __restrict__ hin)
{
    const int tid = threadIdx.x;
#pragma unroll
    for (int r = 0; r < 8; r++) {
        int i = tid + r * 512;
        int bb = i >> 7, kk = i & 127;
        int kg = cch * 128 + kk;
        float v;
        if (kg < 128)      v = emb[(size_t)ids[bb * TT + t] * EE + kg];
        else if (kg < 640) v = g_ctx[bb * H2 + kg - 128];
        else               v = hin[bb * HH + kg - 640];
        sm->sA[bb * 132 + kk] = v;
    }
}

__device__ __forceinline__ void stage_chunk_2(
    Smem* sm, int cch, const float* __restrict__ s0, const float* __restrict__ s1)
{
    const int tid = threadIdx.x;
#pragma unroll
    for (int r = 0; r < 8; r++) {
        int i = tid + r * 512;
        int bb = i >> 7, kk = i & 127;
        int kg = cch * 128 + kk;
        float v = (kg < 256) ? s0[bb * HH + kg] : s1[bb * H2 + kg - 256];
        sm->sA[bb * 132 + kk] = v;
    }
}

__device__ __forceinline__ float dot16(const float* __restrict__ a, const float* __restrict__ w) {
    float4 a0 = *(const float4*)(a + 0), a1 = *(const float4*)(a + 4);
    float4 a2 = *(const float4*)(a + 8), a3 = *(const float4*)(a + 12);
    float4 w0 = *(const float4*)(w + 0), w1 = *(const float4*)(w + 4);
    float4 w2 = *(const float4*)(w + 8), w3 = *(const float4*)(w + 12);
    float s0 = a0.x * w0.x + a0.y * w0.y + a0.z * w0.z + a0.w * w0.w;
    float s1 = a1.x * w1.x + a1.y * w1.y + a1.z * w1.z + a1.w * w1.w;
    float s2 = a2.x * w2.x + a2.y * w2.y + a2.z * w2.z + a2.w * w2.w;
    float s3 = a3.x * w3.x + a3.y * w3.y + a3.z * w3.z + a3.w * w3.w;
    return (s0 + s1) + (s2 + s3);
}

__device__ __forceinline__ void vred_block(
    Smem* sm, int tp, const float* __restrict__ hprev,
    const float* __restrict__ Wvr, const float* __restrict__ bvr, int p)
{
    const int tid = threadIdx.x;
    const int b = tid & 31, jl = (tid >> 5) & 1, kq = tid >> 6;
    const int j = p * 2 + jl;
    float acc = 0.f;
    for (int cch = 0; cch < 6; cch++) {
        __syncthreads();
        stage_chunk_2(sm, cch, hprev, g_ctx);
        __syncthreads();
        int kg = cch * 128 + kq * 16;
        acc += dot16(&sm->sA[b * 132 + kq * 16], &Wvr[(size_t)j * 768 + kg]);
    }
    __syncthreads();
    sm->sred[(jl * 32 + b) * 36 + kq] = acc;
    __syncthreads();
    if (tid < 64) {
        int bb = tid & 31, jjl = tid >> 5, jj = p * 2 + jjl;
        const float* r = &sm->sred[(jjl * 32 + bb) * 36];
        float s = ((r[0] + r[1]) + (r[2] + r[3])) + ((r[4] + r[5]) + (r[6] + r[7]));
        g_vred[((size_t)bb * TT + tp) * HH + jj] = s + bvr[jj];
    }
    __syncthreads();
}

__device__ __forceinline__ void gates_block(
    Smem* sm, int t, const int* __restrict__ ids, const float* __restrict__ emb,
    const float* __restrict__ hin, const float* __restrict__ cin,
    const float* __restrict__ Whh, float* __restrict__ hout, float* __restrict__ cout, int p)
{
    const int tid = threadIdx.x;
    const int b = tid & 31, jl = (tid >> 5) & 1, kq = tid >> 6;
    const int j = p * 2 + jl;
    float a0 = 0.f, a1 = 0.f, a2 = 0.f, a3 = 0.f;
    for (int cch = 0; cch < 7; cch++) {
        __syncthreads();
        stage_chunk_gates(sm, t, cch, ids, emb, hin);
        __syncthreads();
        const float* av = &sm->sA[b * 132 + kq * 16];
        int kg = cch * 128 + kq * 16;
        if (cch < 5) {
            a0 += dot16(av, &g_Wf[(size_t)(0 * 256 + j) * 640 + kg]);
            a1 += dot16(av, &g_Wf[(size_t)(1 * 256 + j) * 640 + kg]);
            a2 += dot16(av, &g_Wf[(size_t)(2 * 256 + j) * 640 + kg]);
            a3 += dot16(av, &g_Wf[(size_t)(3 * 256 + j) * 640 + kg]);
        } else {
            int kh = kg - 640;
            a0 += dot16(av, &Whh[(size_t)(0 * 256 + j) * 256 + kh]);
            a1 += dot16(av, &Whh[(size_t)(1 * 256 + j) * 256 + kh]);
            a2 += dot16(av, &Whh[(size_t)(2 * 256 + j) * 256 + kh]);
            a3 += dot16(av, &Whh[(size_t)(3 * 256 + j) * 256 + kh]);
        }
    }
    __syncthreads();
    float* r = &sm->sred[(jl * 32 + b) * 36 + kq * 4];
    r[0] = a0; r[1] = a1; r[2] = a2; r[3] = a3;
    __syncthreads();
    if (tid < 64) {
        int bb = tid & 31, jjl = tid >> 5, jj = p * 2 + jjl;
        const float* rr = &sm->sred[(jjl * 32 + bb) * 36];
        float s0 = 0.f, s1 = 0.f, s2 = 0.f, s3 = 0.f;
#pragma unroll
        for (int q = 0; q < 8; q++) {
            s0 += rr[q * 4 + 0]; s1 += rr[q * 4 + 1];
            s2 += rr[q * 4 + 2]; s3 += rr[q * 4 + 3];
        }
        float gi = s0 + g_bf[jj];
        float gf = s1 + g_bf[256 + jj];
        float gg = s2 + g_bf[512 + jj];
        float go = s3 + g_bf[768 + jj];
        float co = cin[bb * HH + jj];
        float cn = sigf(gf) * co + sigf(gi) * tanhf(gg);
        float hn = sigf(go) * tanhf(cn);
        cout[bb * HH + jj] = cn;
        hout[bb * HH + jj] = hn;
    }
    __syncthreads();
}

__device__ __forceinline__ void dec_block(
    Smem* sm, const float* __restrict__ hn, const float* __restrict__ cn,
    const float* __restrict__ Wsa, const float* __restrict__ bsa, int p)
{
    const int tid = threadIdx.x;
    const int b = tid & 31, jl = (tid >> 5) & 1, kq = tid >> 6;
    const int j = p * 2 + jl;
    float acc = 0.f;
    for (int cch = 0; cch < 4; cch++) {
        __syncthreads();
        {
            const int t2 = threadIdx.x;
#pragma unroll
            for (int r = 0; r < 8; r++) {
                int i = t2 + r * 512;
                int bb = i >> 7, kk = i & 127;
                int kg = cch * 128 + kk;
                sm->sA[bb * 132 + kk] = (kg < 256) ? hn[bb * HH + kg] : cn[bb * HH + kg - 256];
            }
        }
        __syncthreads();
        int kg = cch * 128 + kq * 16;
        acc += dot16(&sm->sA[b * 132 + kq * 16], &Wsa[(size_t)j * 512 + kg]);
    }
    __syncthreads();
    sm->sred[(jl * 32 + b) * 36 + kq] = acc;
    __syncthreads();
    if (tid < 64) {
        int bb = tid & 31, jjl = tid >> 5, jj = p * 2 + jjl;
        const float* r = &sm->sred[(jjl * 32 + bb) * 36];
        float s = ((r[0] + r[1]) + (r[2] + r[3])) + ((r[4] + r[5]) + (r[6] + r[7]));
        g_dec[bb * HH + jj] = s + bsa[jj];
    }
    __syncthreads();
}

__device__ __forceinline__ void pgen_block(
    Smem* sm, int tp, const int* __restrict__ ids, const float* __restrict__ emb,
    const float* __restrict__ hn, const float* __restrict__ cn,
    const float* __restrict__ whp, const float* __restrict__ wsp,
    float* __restrict__ dout, int p)
{
    const int tid = threadIdx.x;
    const int half = tid >> 8, lt = tid & 255;
    const int b = (p - 128) * 2 + half;
    float acc = 0.f;
    for (int k = lt; k < 512; k += 256) {
        float sv = (k < 256) ? hn[b * HH + k] : cn[b * HH + k - 256];
        acc += whp[k] * g_ctx[b * H2 + k] + wsp[k] * sv;
    }
    int id = ids[b * TT + tp];
    for (int k = lt; k < 640; k += 256) {
        float av = (k < 128) ? emb[(size_t)id * EE + k] : g_ctx[b * H2 + k - 128];
        acc += g_wxr[k] * av;
    }
    sm->spg[tid] = acc;
    __syncthreads();
#pragma unroll
    for (int o = 128; o > 0; o >>= 1) {
        if (lt < o) sm->spg[half * 256 + lt] += sm->spg[half * 256 + lt + o];
        __syncthreads();
    }
    if (lt == 0)
        dout[OFF_PG + (size_t)b * TT + tp] = sigf(sm->spg[half * 256] + g_wxr[640]);
    __syncthreads();
}

__global__ __launch_bounds__(TPB, 1) void k_persistent(
    const int* __restrict__ ids, const float* __restrict__ emb,
    const float* __restrict__ enc, const unsigned char* __restrict__ mask,
    const float* __restrict__ Whh, const float* __restrict__ Wsa,
    const float* __restrict__ bsa, const float* __restrict__ va,
    const float* __restrict__ whp, const float* __restrict__ wsp,
    const float* __restrict__ Wvr, const float* __restrict__ bvr,
    float* __restrict__ dout)
{
    __shared__ Smem sm;
    const int p = blockIdx.x, tid = threadIdx.x;
    unsigned target = 0;

    for (int t = 0; t < TT; t++) {
        const float* hin = g_h[t & 1];
        const float* cin = g_c[t & 1];
        float* hout = g_h[(t + 1) & 1];
        float* cout = g_c[(t + 1) & 1];

        if (p < 128) {
            if (t > 0) vred_block(&sm, t - 1, hin, Wvr, bvr, p);
            gates_block(&sm, t, ids, emb, hin, cin, Whh, hout, cout, p);
        } else if (p < 144) {
            if (t > 0) pgen_block(&sm, t - 1, ids, emb, hin, cin, whp, wsp, dout, p);
        }
        gbarrier(target);

        if (p < 128) dec_block(&sm, hout, cout, Wsa, bsa, p);
        gbarrier(target);

        {
            const int w = tid >> 5, lane = tid & 31;
#pragma unroll
            for (int i = 0; i < 6; i++) {
                int u = p * 16 + w + i * (NB * 16);
                if (u < BB * SS) {
                    int b = u / SS;
                    const float4* ef = (const float4*)(g_enc_feat + (size_t)u * HH);
                    const float4* dp = (const float4*)(g_dec + b * HH);
                    const float4* vp = (const float4*)va;
                    float acc = 0.f;
#pragma unroll
                    for (int h = 0; h < 2; h++) {
                        int ix = lane + h * 32;
                        float4 e = ef[ix], d = dp[ix], v = vp[ix];
                        acc += v.x * ftanh(e.x + d.x) + v.y * ftanh(e.y + d.y)
                             + v.z * ftanh(e.z + d.z) + v.w * ftanh(e.w + d.w);
                    }
#pragma unroll
                    for (int o = 16; o > 0; o >>= 1) acc += __shfl_xor_sync(0xffffffffu, acc, o);
                    if (lane == 0) g_scores[u] = mask[u] ? NEG_INF : acc;
                }
            }
        }
        gbarrier(target);

        if (p < 128) {
            const int b = p >> 2, ch = p & 3;
            float sc = (tid < SS) ? g_scores[b * SS + tid] : NEG_INF;
            sm.red[tid] = sc;
            __syncthreads();
#pragma unroll
            for (int o = 256; o > 0; o >>= 1) {
                if (tid < o) sm.red[tid] = fmaxf(sm.red[tid], sm.red[tid + o]);
                __syncthreads();
            }
            float m = sm.red[0];
            __syncthreads();
            float e = (tid < SS) ? expf(sc - m) : 0.f;
            sm.red[tid] = e;
            __syncthreads();
#pragma unroll
            for (int o = 256; o > 0; o >>= 1) {
                if (tid < o) sm.red[tid] += sm.red[tid + o];
                __syncthreads();
            }
            float inv = 1.0f / sm.red[0];
            __syncthreads();
            if (tid < SS) {
                float a = e * inv;
                sm.sat[tid] = a;
                if (ch == 0) dout[OFF_ATTN + ((size_t)b * TT + t) * SS + tid] = a;
            }
            __syncthreads();
            const int d = tid & 127, sg = tid >> 7;
            const float* ep = enc + ((size_t)b * SS + sg * 100) * H2 + ch * 128 + d;
            float acc = 0.f;
#pragma unroll 4
            for (int s = 0; s < 100; s++) acc += sm.sat[sg * 100 + s] * ep[(size_t)s * H2];
            sm.spart[sg * 128 + d] = acc;
            __syncthreads();
            if (tid < 128) {
                float v = (sm.spart[tid] + sm.spart[128 + tid])
                        + (sm.spart[256 + tid] + sm.spart[384 + tid]);
                g_ctx[b * H2 + ch * 128 + tid] = v;
            }
        }
        gbarrier(target);
    }

    const float* hf = g_h[0];
    const float* cf = g_c[0];
    if (p < 128) {
        vred_block(&sm, TT - 1, hf, Wvr, bvr, p);
    } else if (p < 144) {
        pgen_block(&sm, TT - 1, ids, emb, hf, cf, whp, wsp, dout, p);
    } else {
        for (int i0 = (p - 144) * 2048 + tid; i0 < (p - 143) * 2048; i0 += TPB) {
            dout[OFF_H + i0] = hf[i0];
            dout[OFF_C + i0] = cf[i0];
        }
    }
}

// ---------------- row softmax over V (in place in d_out), grid 2048, float4 ----------------
__global__ __launch_bounds__(512) void k_vsoftmax(float* __restrict__ out)
{
    const int r = blockIdx.x, tid = threadIdx.x;
    float4* row4 = (float4*)(out + (size_t)r * VV);
    float m = NEG_INF, s = 0.0f;
    for (int v = tid; v < VV / 4; v += 512) {
        float4 l4 = row4[v];
        float lm = fmaxf(fmaxf(l4.x, l4.y), fmaxf(l4.z, l4.w));
        if (lm > m) { s = s * expf(m - lm); m = lm; }
        s += expf(l4.x - m) + expf(l4.y - m) + expf(l4.z - m) + expf(l4.w - m);
    }
    __shared__ float smx[512], ssm[512];
    smx[tid] = m; ssm[tid] = s;
    __syncthreads();
#pragma unroll
    for (int o = 256; o > 0; o >>= 1) {
        if (tid < o) {
            float m2 = fmaxf(smx[tid], smx[tid + o]);
            ssm[tid] = ssm[tid] * expf(smx[tid] - m2) + ssm[tid + o] * expf(smx[tid + o] - m2);
            smx[tid] = m2;
        }
        __syncthreads();
    }
    float M = smx[0], inv = 1.0f / ssm[0];
    for (int v = tid; v < VV / 4; v += 512) {
        float4 l4 = row4[v];
        l4.x = expf(l4.x - M) * inv;
        l4.y = expf(l4.y - M) * inv;
        l4.z = expf(l4.z - M) * inv;
        l4.w = expf(l4.w - M) * inv;
        row4[v] = l4;
    }
}

// ---------------- host ----------------
extern "C" void kernel_launch(void* const* d_in, const int* in_sizes, int n_in,
                              void* d_out, int out_size)
{
    const int*   ids  = (const int*)d_in[0];
    const float* h0   = (const float*)d_in[1];
    const float* c0   = (const float*)d_in[2];
    const float* enc  = (const float*)d_in[3];
    const unsigned char* mask = (const unsigned char*)d_in[4];
    const float* emb  = (const float*)d_in[5];
    const float* Wr   = (const float*)d_in[6];
    const float* br   = (const float*)d_in[7];
    const float* Wih  = (const float*)d_in[8];
    const float* Whh  = (const float*)d_in[9];
    const float* bih  = (const float*)d_in[10];
    const float* bhh  = (const float*)d_in[11];
    const float* Wh_a = (const float*)d_in[12];
    const float* Ws_a = (const float*)d_in[13];
    const float* bs_a = (const float*)d_in[14];
    const float* v_a  = (const float*)d_in[15];
    const float* wh_p = (const float*)d_in[16];
    const float* ws_p = (const float*)d_in[17];
    const float* wx_p = (const float*)d_in[18];
    const float* bx_p = (const float*)d_in[19];
    const float* Wvr  = (const float*)d_in[20];
    const float* bvr  = (const float*)d_in[21];
    const float* Wvo  = (const float*)d_in[22];
    const float* bvo  = (const float*)d_in[23];
    float* out = (float*)d_out;

    float *encf = nullptr, *vredp = nullptr, *Wfp = nullptr;
    __nv_bfloat16 *vredbf = nullptr, *wvobf = nullptr;
    cudaGetSymbolAddress((void**)&encf,   g_enc_feat);
    cudaGetSymbolAddress((void**)&vredp,  g_vred);
    cudaGetSymbolAddress((void**)&Wfp,    g_Wf);
    cudaGetSymbolAddress((void**)&vredbf, g_vred_bf);
    cudaGetSymbolAddress((void**)&wvobf,  g_Wvo_bf);

    // prep: barrier reset, fused biases, folded pgen vector, h/c/ctx init
    k_prep<<<8, 256>>>(Wih, br, bih, bhh, Wr, wx_p, bx_p);
    k_init<<<64, 256>>>(h0, c0);

    // Wf = Wih[1024,256] @ Wr[256,640]
    sgemm_abn<<<dim3(5, 8), 256>>>(Wih, Wr, Wfp, 1024, 640, 256);

    // enc_feat = enc @ Wh_a^T (loop-invariant)
    sgemm_abt<<<dim3(2, 100), 256>>>(enc, Wh_a, nullptr, encf, BB * SS, HH, H2);

    // Wvo fp32 -> bf16 (independent of the recurrence)
    k_cvt<<<(VV * HH / 4 + 255) / 256, 256>>>(Wvo, wvobf, VV * HH / 4);

    // full 64-step recurrence in one persistent kernel
    k_persistent<<<NB, TPB>>>(ids, emb, enc, mask, Whh, Ws_a, bs_a, v_a,
                              wh_p, ws_p, Wvr, bvr, out);

    // vred fp32 -> bf16, then tensor-core vocab projection + softmax
    k_cvt<<<(BB * TT * HH / 4 + 255) / 256, 256>>>(vredp, vredbf, BB * TT * HH / 4);
    hgemm_vocab<<<dim3(391, 16), 256>>>(vredbf, wvobf, bvo, out);
    k_vsoftmax<<<BB * TT, 512>>>(out);
}

// round 12
// speedup vs baseline: 4.8886x; 1.4525x over previous
#include <cuda_runtime.h>
#include <cuda_bf16.h>
#include <math.h>
#include <cstdint>

#define BB 32
#define TT 64
#define SS 400
#define HH 256
#define EE 128
#define VV 50000
#define H2 512

#define NB  148
#define TPB 512

// d_out layout (fp32): vocab_dists[B,T,V], attn[B,T,S], pgen[B,T,1], h[B,H], c[B,H]
#define OFF_ATTN 102400000ull
#define OFF_PG   103219200ull
#define OFF_H    103221248ull
#define OFF_C    103229440ull

// ---------------- scratch ----------------
__device__ unsigned g_cnt;
__device__ float g_Wf[1024 * 640];      // Wih @ Wr  [4H, 640]  (fp32 on purpose)
__device__ float g_bf[1024];            // bih + bhh + Wih @ br
__device__ float g_wxr[641];            // Wr^T @ wx_p ; [640] = wx_p.br + bx_p
__device__ float g_enc_feat[BB * SS * HH];
__device__ float g_h[2][BB * HH];
__device__ float g_c[2][BB * HH];
__device__ float g_ctx[BB * H2];
__device__ float g_dec[BB * HH];
__device__ float g_scores[BB * SS];
__device__ float g_vred[BB * TT * HH];          // rows r = b*T+t
__device__ __nv_bfloat16 g_vred_bf[BB * TT * HH];
__device__ __nv_bfloat16 g_Wvo_bf[VV * HH];
__device__ __nv_bfloat16 g_enc_bf[BB * SS * H2];
__device__ __nv_bfloat16 g_Wha_bf[HH * H2];

__device__ __forceinline__ float sigf(float v) { return 1.0f / (1.0f + expf(-v)); }
__device__ __forceinline__ float ftanh(float x) {
    float r; asm("tanh.approx.f32 %0, %1;" : "=f"(r) : "f"(x)); return r;
}
#define NEG_INF __int_as_float(0xff800000)

// ---------------- packed fp32x2 FMA helpers ----------------
__device__ __forceinline__ void fma2(unsigned long long& d,
                                     unsigned long long a, unsigned long long b) {
    asm("fma.rn.f32x2 %0, %1, %2, %0;" : "+l"(d) : "l"(a), "l"(b));
}
__device__ __forceinline__ float unpack_add(unsigned long long v) {
    float lo = __uint_as_float((unsigned)(v & 0xffffffffull));
    float hi = __uint_as_float((unsigned)(v >> 32));
    return lo + hi;
}
// acc += dot(a[0:16], w[0:16]) on two packed lanes
__device__ __forceinline__ void dot16p(unsigned long long& acc,
                                       const float* __restrict__ a,
                                       const float* __restrict__ w) {
    ulonglong2 A0 = *(const ulonglong2*)(a + 0), A1 = *(const ulonglong2*)(a + 4);
    ulonglong2 A2 = *(const ulonglong2*)(a + 8), A3 = *(const ulonglong2*)(a + 12);
    ulonglong2 W0 = *(const ulonglong2*)(w + 0), W1 = *(const ulonglong2*)(w + 4);
    ulonglong2 W2 = *(const ulonglong2*)(w + 8), W3 = *(const ulonglong2*)(w + 12);
    fma2(acc, A0.x, W0.x); fma2(acc, A0.y, W0.y);
    fma2(acc, A1.x, W1.x); fma2(acc, A1.y, W1.y);
    fma2(acc, A2.x, W2.x); fma2(acc, A2.y, W2.y);
    fma2(acc, A3.x, W3.x); fma2(acc, A3.y, W3.y);
}

__device__ __forceinline__ float wredmax(float v) {
#pragma unroll
    for (int o = 16; o > 0; o >>= 1) v = fmaxf(v, __shfl_xor_sync(0xffffffffu, v, o));
    return v;
}
__device__ __forceinline__ float wredsum(float v) {
#pragma unroll
    for (int o = 16; o > 0; o >>= 1) v += __shfl_xor_sync(0xffffffffu, v, o);
    return v;
}

// ---------------- grid-wide software barrier ----------------
__device__ __forceinline__ void gbarrier(unsigned& target) {
    __syncthreads();
    if (threadIdx.x == 0) {
        unsigned* pc = &g_cnt;
        asm volatile("red.release.gpu.global.add.u32 [%0], 1;" :: "l"(pc) : "memory");
        target += NB;
        unsigned v;
        asm volatile("ld.acquire.gpu.global.u32 %0, [%1];" : "=r"(v) : "l"(pc) : "memory");
        while (v < target) {
            asm volatile("nanosleep.u32 128;");
            asm volatile("ld.acquire.gpu.global.u32 %0, [%1];" : "=r"(v) : "l"(pc) : "memory");
        }
    }
    __syncthreads();
}

// ---------------- prep ----------------
__global__ void k_prep(const float* __restrict__ Wih, const float* __restrict__ br,
                       const float* __restrict__ bih, const float* __restrict__ bhh,
                       const float* __restrict__ Wr, const float* __restrict__ wxp,
                       const float* __restrict__ bxp) {
    int p = blockIdx.x, tid = threadIdx.x;
    if (p == 0 && tid == 0) g_cnt = 0;
    if (p < 4) {
        int n = p * 256 + tid;
        float acc = bih[n] + bhh[n];
        const float* w = Wih + (size_t)n * 256;
        for (int m = 0; m < 256; m++) acc += w[m] * br[m];
        g_bf[n] = acc;
    } else if (p < 7) {
        int k = (p - 4) * 256 + tid;
        if (k < 640) {
            float acc = 0.f;
            for (int m = 0; m < 256; m++) acc += wxp[m] * Wr[(size_t)m * 640 + k];
            g_wxr[k] = acc;
        }
    } else if (tid == 0) {
        float acc = bxp[0];
        for (int m = 0; m < 256; m++) acc += wxp[m] * br[m];
        g_wxr[640] = acc;
    }
}

__global__ void k_init(const float* __restrict__ h0, const float* __restrict__ c0) {
    int i = blockIdx.x * 256 + threadIdx.x;
    if (i < BB * HH) { g_h[0][i] = h0[i]; g_c[0][i] = c0[i]; }
    if (i < BB * H2) g_ctx[i] = 0.0f;
}

// ---------------- fp32 -> bf16 ----------------
__global__ void k_cvt(const float* __restrict__ in, __nv_bfloat16* __restrict__ out, int n4)
{
    int i = blockIdx.x * 256 + threadIdx.x;
    if (i < n4) {
        float4 v = ((const float4*)in)[i];
        ((__nv_bfloat162*)out)[i * 2 + 0] = __floats2bfloat162_rn(v.x, v.y);
        ((__nv_bfloat162*)out)[i * 2 + 1] = __floats2bfloat162_rn(v.z, v.w);
    }
}

// ---------------- fp32 GEMM (Wf precompute): C[M,N] = A[M,K] @ Bn[K,N] ----------------
__global__ __launch_bounds__(256) void sgemm_abn(
    const float* __restrict__ A, const float* __restrict__ Bn,
    float* __restrict__ C, int M, int N, int K)
{
    __shared__ float As[8][128];
    __shared__ float Bs[8][128];
    const int tid = threadIdx.x;
    const int row0 = blockIdx.y << 7;
    const int col0 = blockIdx.x << 7;
    const int tr = (tid >> 4) << 3;
    const int tc = (tid & 15) << 3;
    float acc[8][8];
#pragma unroll
    for (int i = 0; i < 8; i++)
#pragma unroll
        for (int j = 0; j < 8; j++) acc[i][j] = 0.0f;
    const int lr = tid >> 1, lk = (tid & 1) << 2;
    const int blc = (tid & 31) << 2, blk = tid >> 5;
    for (int k0 = 0; k0 < K; k0 += 8) {
        float4 av = *(const float4*)&A[(size_t)(row0 + lr) * K + k0 + lk];
        As[lk + 0][lr] = av.x; As[lk + 1][lr] = av.y; As[lk + 2][lr] = av.z; As[lk + 3][lr] = av.w;
        float4 bv = *(const float4*)&Bn[(size_t)(k0 + blk) * N + col0 + blc];
        Bs[blk][blc + 0] = bv.x; Bs[blk][blc + 1] = bv.y; Bs[blk][blc + 2] = bv.z; Bs[blk][blc + 3] = bv.w;
        __syncthreads();
#pragma unroll
        for (int kk = 0; kk < 8; kk++) {
            float4 a0 = *(const float4*)&As[kk][tr];
            float4 a1 = *(const float4*)&As[kk][tr + 4];
            float4 b0 = *(const float4*)&Bs[kk][tc];
            float4 b1 = *(const float4*)&Bs[kk][tc + 4];
            float a[8] = {a0.x, a0.y, a0.z, a0.w, a1.x, a1.y, a1.z, a1.w};
            float b[8] = {b0.x, b0.y, b0.z, b0.w, b1.x, b1.y, b1.z, b1.w};
#pragma unroll
            for (int i = 0; i < 8; i++)
#pragma unroll
                for (int j = 0; j < 8; j++) acc[i][j] += a[i] * b[j];
        }
        __syncthreads();
    }
#pragma unroll
    for (int i = 0; i < 8; i++) {
        size_t r = row0 + tr + i;
#pragma unroll
        for (int j = 0; j < 8; j++)
            C[r * (size_t)N + col0 + tc + j] = acc[i][j];
    }
}

// ================= bf16 tensor-core GEMM: C[M,N] = A[M,K] @ W[N,K]^T (+bias) =============
// Block tile 128x128, 8 warps (2m x 4n), BK=64. M%128==0, K%64==0; N guarded.

__device__ __forceinline__ void ldm_x4(unsigned* r, const void* p) {
    unsigned a = (unsigned)__cvta_generic_to_shared(p);
    asm volatile("ldmatrix.sync.aligned.m8n8.x4.shared.b16 {%0,%1,%2,%3}, [%4];"
        : "=r"(r[0]), "=r"(r[1]), "=r"(r[2]), "=r"(r[3]) : "r"(a));
}
__device__ __forceinline__ void mma16816(float* c, const unsigned* a, unsigned b0, unsigned b1) {
    asm volatile("mma.sync.aligned.m16n8k16.row.col.f32.bf16.bf16.f32 "
        "{%0,%1,%2,%3}, {%4,%5,%6,%7}, {%8,%9}, {%0,%1,%2,%3};"
        : "+f"(c[0]), "+f"(c[1]), "+f"(c[2]), "+f"(c[3])
        : "r"(a[0]), "r"(a[1]), "r"(a[2]), "r"(a[3]), "r"(b0), "r"(b1));
}

__global__ __launch_bounds__(256) void hgemm_nt(
    const __nv_bfloat16* __restrict__ A,
    const __nv_bfloat16* __restrict__ W,
    const float* __restrict__ bias, float* __restrict__ C,
    int M, int N, int K)
{
    __shared__ __nv_bfloat16 As[128][72];
    __shared__ __nv_bfloat16 Ws[128][72];
    const int n0 = blockIdx.x << 7;
    const int m0 = blockIdx.y << 7;
    const int tid = threadIdx.x;
    const int warp = tid >> 5, lane = tid & 31;
    const int wm = (warp & 1) << 6;
    const int wn = (warp >> 1) << 5;

    float acc[4][4][4];
#pragma unroll
    for (int i = 0; i < 4; i++)
#pragma unroll
        for (int j = 0; j < 4; j++)
#pragma unroll
            for (int q = 0; q < 4; q++) acc[i][j][q] = 0.f;

    for (int k0 = 0; k0 < K; k0 += 64) {
#pragma unroll
        for (int r = 0; r < 4; r++) {
            int i = tid + r * 256;
            int row = i >> 3, c = (i & 7) * 8;
            *(uint4*)&As[row][c] = *(const uint4*)&A[(size_t)(m0 + row) * K + k0 + c];
            uint4 v = make_uint4(0u, 0u, 0u, 0u);
            if (n0 + row < N)
                v = *(const uint4*)&W[(size_t)(n0 + row) * K + k0 + c];
            *(uint4*)&Ws[row][c] = v;
        }
        __syncthreads();
#pragma unroll
        for (int ks = 0; ks < 64; ks += 16) {
            unsigned af[4][4];
#pragma unroll
            for (int ma = 0; ma < 4; ma++)
                ldm_x4(af[ma], &As[wm + ma * 16 + (lane & 15)][ks + (lane >> 4) * 8]);
            unsigned bfr[2][4];
#pragma unroll
            for (int nb = 0; nb < 2; nb++)
                ldm_x4(bfr[nb], &Ws[wn + nb * 16 + (lane & 15)][ks + (lane >> 4) * 8]);
#pragma unroll
            for (int ma = 0; ma < 4; ma++)
#pragma unroll
                for (int na = 0; na < 4; na++)
                    mma16816(acc[ma][na], af[ma],
                             bfr[na >> 1][na & 1], bfr[na >> 1][2 + (na & 1)]);
        }
        __syncthreads();
    }
#pragma unroll
    for (int ma = 0; ma < 4; ma++) {
        int r0 = m0 + wm + ma * 16 + (lane >> 2);
#pragma unroll
        for (int na = 0; na < 4; na++) {
            int c = n0 + wn + na * 8 + (lane & 3) * 2;
            if (c < N) {
                float b0 = bias ? bias[c] : 0.f;
                float b1 = bias ? bias[c + 1] : 0.f;
                float2 v0 = make_float2(acc[ma][na][0] + b0, acc[ma][na][1] + b1);
                float2 v1 = make_float2(acc[ma][na][2] + b0, acc[ma][na][3] + b1);
                *(float2*)&C[(size_t)r0 * N + c] = v0;
                *(float2*)&C[(size_t)(r0 + 8) * N + c] = v1;
            }
        }
    }
}

// ================= persistent recurrence kernel =================
// sA holds staged activations in 7 chunks of [32 b][132 pitch] (128 k per chunk).
struct Smem {
    float sA[7 * 32 * 132];   // 118 KB
    float sred[64 * 36];
    float sat[SS];
    float red[64];
    float spart[512];
    float spg[512];
};

__device__ __forceinline__ void pgen_block(
    Smem* sm, int tp, const int* __restrict__ ids, const float* __restrict__ emb,
    const float* __restrict__ hn, const float* __restrict__ cn,
    const float* __restrict__ whp, const float* __restrict__ wsp,
    float* __restrict__ dout, int p)
{
    const int tid = threadIdx.x;
    const int half = tid >> 8, lt = tid & 255;
    const int b = (p - 128) * 2 + half;
    float acc = 0.f;
    for (int k = lt; k < 512; k += 256) {
        float sv = (k < 256) ? hn[b * HH + k] : cn[b * HH + k - 256];
        acc += whp[k] * g_ctx[b * H2 + k] + wsp[k] * sv;
    }
    int id = ids[b * TT + tp];
    for (int k = lt; k < 640; k += 256) {
        float av = (k < 128) ? emb[(size_t)id * EE + k] : g_ctx[b * H2 + k - 128];
        acc += g_wxr[k] * av;
    }
    sm->spg[tid] = acc;
    __syncthreads();
#pragma unroll
    for (int o = 128; o > 0; o >>= 1) {
        if (lt < o) sm->spg[half * 256 + lt] += sm->spg[half * 256 + lt + o];
        __syncthreads();
    }
    if (lt == 0)
        dout[OFF_PG + (size_t)b * TT + tp] = sigf(sm->spg[half * 256] + g_wxr[640]);
    __syncthreads();
}

__global__ __launch_bounds__(TPB, 1) void k_persistent(
    const int* __restrict__ ids, const float* __restrict__ emb,
    const float* __restrict__ enc, const unsigned char* __restrict__ mask,
    const float* __restrict__ Whh, const float* __restrict__ Wsa,
    const float* __restrict__ bsa, const float* __restrict__ va,
    const float* __restrict__ whp, const float* __restrict__ wsp,
    const float* __restrict__ Wvr, const float* __restrict__ bvr,
    float* __restrict__ dout)
{
    extern __shared__ char smraw[];
    Smem* sm = (Smem*)smraw;
    const int p = blockIdx.x, tid = threadIdx.x;
    const int b = tid & 31, jl = (tid >> 5) & 1, kq = tid >> 6;
    unsigned target = 0;

    for (int t = 0; t < TT; t++) {
        const float* hin = g_h[t & 1];
        const float* cin = g_c[t & 1];
        float* hout = g_h[(t + 1) & 1];
        float* cout = g_c[(t + 1) & 1];

        // ================= P1: stage [emb|ctx|h] once; vred(t-1) + gates(t) ======
        if (p < 128) {
            const int j = p * 2 + jl;
            // stage: 32 b x 224 float4 = 7168 -> 14 per thread
#pragma unroll
            for (int r = 0; r < 14; r++) {
                int idx = tid + r * 512;
                int bb = idx / 224;
                int q = idx - bb * 224;
                float4 v;
                if (q < 32)       v = ((const float4*)(emb + (size_t)ids[bb * TT + t] * EE))[q];
                else if (q < 160) v = ((const float4*)(g_ctx + bb * H2))[q - 32];
                else              v = ((const float4*)(hin + bb * HH))[q - 160];
                int k = q * 4, cch = k >> 7, kk = k & 127;
                *(float4*)&sm->sA[(cch * 32 + bb) * 132 + kk] = v;
            }
            __syncthreads();

            // vred(t-1): remap vred-k -> gates chunks (h: 5,6 ; ctx: 1..4)
            unsigned long long accv = 0ull;
            if (t > 0) {
                const float* wv = Wvr + (size_t)j * 768;
#pragma unroll
                for (int cv = 0; cv < 6; cv++) {
                    int gc = (cv < 2) ? (5 + cv) : (cv - 1);
                    dot16p(accv, &sm->sA[(gc * 32 + b) * 132 + kq * 16],
                           wv + cv * 128 + kq * 16);
                }
            }
            // gates(t)
            unsigned long long ag0 = 0ull, ag1 = 0ull, ag2 = 0ull, ag3 = 0ull;
#pragma unroll
            for (int cch = 0; cch < 7; cch++) {
                const float* av = &sm->sA[(cch * 32 + b) * 132 + kq * 16];
                if (cch < 5) {
                    int kg = cch * 128 + kq * 16;
                    dot16p(ag0, av, &g_Wf[(size_t)(0 * 256 + j) * 640 + kg]);
                    dot16p(ag1, av, &g_Wf[(size_t)(1 * 256 + j) * 640 + kg]);
                    dot16p(ag2, av, &g_Wf[(size_t)(2 * 256 + j) * 640 + kg]);
                    dot16p(ag3, av, &g_Wf[(size_t)(3 * 256 + j) * 640 + kg]);
                } else {
                    int kh = cch * 128 + kq * 16 - 640;
                    dot16p(ag0, av, &Whh[(size_t)(0 * 256 + j) * 256 + kh]);
                    dot16p(ag1, av, &Whh[(size_t)(1 * 256 + j) * 256 + kh]);
                    dot16p(ag2, av, &Whh[(size_t)(2 * 256 + j) * 256 + kh]);
                    dot16p(ag3, av, &Whh[(size_t)(3 * 256 + j) * 256 + kh]);
                }
            }
            if (t > 0) {
                sm->sred[(jl * 32 + b) * 36 + kq] = unpack_add(accv);
                __syncthreads();
                if (tid < 64) {
                    int bb2 = tid & 31, jjl = tid >> 5, jj = p * 2 + jjl;
                    const float* r = &sm->sred[(jjl * 32 + bb2) * 36];
                    float s = ((r[0] + r[1]) + (r[2] + r[3])) + ((r[4] + r[5]) + (r[6] + r[7]));
                    g_vred[((size_t)bb2 * TT + (t - 1)) * HH + jj] = s + bvr[jj];
                }
                __syncthreads();
            }
            {
                float* r = &sm->sred[(jl * 32 + b) * 36 + kq * 4];
                r[0] = unpack_add(ag0); r[1] = unpack_add(ag1);
                r[2] = unpack_add(ag2); r[3] = unpack_add(ag3);
            }
            __syncthreads();
            if (tid < 64) {
                int bb2 = tid & 31, jjl = tid >> 5, jj = p * 2 + jjl;
                const float* rr = &sm->sred[(jjl * 32 + bb2) * 36];
                float s0 = 0.f, s1 = 0.f, s2 = 0.f, s3 = 0.f;
#pragma unroll
                for (int q = 0; q < 8; q++) {
                    s0 += rr[q * 4 + 0]; s1 += rr[q * 4 + 1];
                    s2 += rr[q * 4 + 2]; s3 += rr[q * 4 + 3];
                }
                float gi = s0 + g_bf[jj];
                float gf = s1 + g_bf[256 + jj];
                float gg = s2 + g_bf[512 + jj];
                float go = s3 + g_bf[768 + jj];
                float co = cin[bb2 * HH + jj];
                float cn = sigf(gf) * co + sigf(gi) * tanhf(gg);
                float hn = sigf(go) * tanhf(cn);
                cout[bb2 * HH + jj] = cn;
                hout[bb2 * HH + jj] = hn;
            }
        } else if (p < 144) {
            if (t > 0) pgen_block(sm, t - 1, ids, emb, hin, cin, whp, wsp, dout, p);
        }
        gbarrier(target);

        // ================= P2: dec = [h|c] @ Wsa^T + bsa ==========================
        if (p < 128) {
            const int j = p * 2 + jl;
#pragma unroll
            for (int r = 0; r < 8; r++) {
                int idx = tid + r * 512;
                int bb = idx >> 7, q = idx & 127;
                float4 v = (q < 64) ? ((const float4*)(hout + bb * HH))[q]
                                    : ((const float4*)(cout + bb * HH))[q - 64];
                int k = q * 4, cch = k >> 7, kk = k & 127;
                *(float4*)&sm->sA[(cch * 32 + bb) * 132 + kk] = v;
            }
            __syncthreads();
            unsigned long long acc = 0ull;
#pragma unroll
            for (int cch = 0; cch < 4; cch++)
                dot16p(acc, &sm->sA[(cch * 32 + b) * 132 + kq * 16],
                       Wsa + (size_t)j * 512 + cch * 128 + kq * 16);
            sm->sred[(jl * 32 + b) * 36 + kq] = unpack_add(acc);
            __syncthreads();
            if (tid < 64) {
                int bb2 = tid & 31, jjl = tid >> 5, jj = p * 2 + jjl;
                const float* r = &sm->sred[(jjl * 32 + bb2) * 36];
                float s = ((r[0] + r[1]) + (r[2] + r[3])) + ((r[4] + r[5]) + (r[6] + r[7]));
                g_dec[bb2 * HH + jj] = s + bsa[jj];
            }
        }
        gbarrier(target);

        // ================= P3: scores ============================================
        {
            const int w = tid >> 5, lane = tid & 31;
#pragma unroll
            for (int i = 0; i < 6; i++) {
                int u = p * 16 + w + i * (NB * 16);
                if (u < BB * SS) {
                    int bu = u / SS;
                    const float4* ef = (const float4*)(g_enc_feat + (size_t)u * HH);
                    const float4* dp = (const float4*)(g_dec + bu * HH);
                    const float4* vp = (const float4*)va;
                    float acc = 0.f;
#pragma unroll
                    for (int h = 0; h < 2; h++) {
                        int ix = lane + h * 32;
                        float4 e = ef[ix], d = dp[ix], v = vp[ix];
                        acc += v.x * ftanh(e.x + d.x) + v.y * ftanh(e.y + d.y)
                             + v.z * ftanh(e.z + d.z) + v.w * ftanh(e.w + d.w);
                    }
#pragma unroll
                    for (int o = 16; o > 0; o >>= 1) acc += __shfl_xor_sync(0xffffffffu, acc, o);
                    if (lane == 0) g_scores[u] = mask[u] ? NEG_INF : acc;
                }
            }
        }
        gbarrier(target);

        // ================= P4: softmax + ctx =====================================
        if (p < 128) {
            const int bq = p >> 2, ch = p & 3;
            const int w = tid >> 5, lane = tid & 31;
            float sc = (tid < SS) ? g_scores[bq * SS + tid] : NEG_INF;
            float wm = wredmax(sc);
            if (lane == 0) sm->red[w] = wm;
            __syncthreads();
            if (w == 0) {
                float m2 = (lane < 16) ? sm->red[lane] : NEG_INF;
                m2 = wredmax(m2);
                if (lane == 0) sm->red[32] = m2;
            }
            __syncthreads();
            float m = sm->red[32];
            float e = (tid < SS) ? expf(sc - m) : 0.f;
            float wsv = wredsum(e);
            if (lane == 0) sm->red[w] = wsv;
            __syncthreads();
            if (w == 0) {
                float s2 = (lane < 16) ? sm->red[lane] : 0.f;
                s2 = wredsum(s2);
                if (lane == 0) sm->red[33] = 1.0f / s2;
            }
            __syncthreads();
            float inv = sm->red[33];
            if (tid < SS) {
                float a = e * inv;
                sm->sat[tid] = a;
                if (ch == 0) dout[OFF_ATTN + ((size_t)bq * TT + t) * SS + tid] = a;
            }
            __syncthreads();
            const int d = tid & 127, sg = tid >> 7;
            const float* ep = enc + ((size_t)bq * SS + sg * 100) * H2 + ch * 128 + d;
            float acc = 0.f;
#pragma unroll 10
            for (int s = 0; s < 100; s++) acc += sm->sat[sg * 100 + s] * ep[(size_t)s * H2];
            sm->spart[sg * 128 + d] = acc;
            __syncthreads();
            if (tid < 128) {
                float v = (sm->spart[tid] + sm->spart[128 + tid])
                        + (sm->spart[256 + tid] + sm->spart[384 + tid]);
                g_ctx[bq * H2 + ch * 128 + tid] = v;
            }
        }
        gbarrier(target);
    }

    // ================= tail: vred(63), pgen(63), final h/c ======================
    const float* hf = g_h[0];
    const float* cf = g_c[0];
    if (p < 128) {
        const int j = p * 2 + jl;
        // stage [h|ctx] (768) in direct vred order: 6144 f4 -> 12/thread
#pragma unroll
        for (int r = 0; r < 12; r++) {
            int idx = tid + r * 512;
            int bb = idx / 192;
            int q = idx - bb * 192;
            float4 v = (q < 64) ? ((const float4*)(hf + bb * HH))[q]
                                : ((const float4*)(g_ctx + bb * H2))[q - 64];
            int k = q * 4, cch = k >> 7, kk = k & 127;
            *(float4*)&sm->sA[(cch * 32 + bb) * 132 + kk] = v;
        }
        __syncthreads();
        unsigned long long acc = 0ull;
#pragma unroll
        for (int cv = 0; cv < 6; cv++)
            dot16p(acc, &sm->sA[(cv * 32 + b) * 132 + kq * 16],
                   Wvr + (size_t)j * 768 + cv * 128 + kq * 16);
        sm->sred[(jl * 32 + b) * 36 + kq] = unpack_add(acc);
        __syncthreads();
        if (tid < 64) {
            int bb2 = tid & 31, jjl = tid >> 5, jj = p * 2 + jjl;
            const float* r = &sm->sred[(jjl * 32 + bb2) * 36];
            float s = ((r[0] + r[1]) + (r[2] + r[3])) + ((r[4] + r[5]) + (r[6] + r[7]));
            g_vred[((size_t)bb2 * TT + (TT - 1)) * HH + jj] = s + bvr[jj];
        }
    } else if (p < 144) {
        pgen_block(sm, TT - 1, ids, emb, hf, cf, whp, wsp, dout, p);
    } else {
        for (int i0 = (p - 144) * 2048 + tid; i0 < (p - 143) * 2048; i0 += TPB) {
            dout[OFF_H + i0] = hf[i0];
            dout[OFF_C + i0] = cf[i0];
        }
    }
}

// ---------------- row softmax over V (in place), grid 2048, float4 ----------------
__global__ __launch_bounds__(512) void k_vsoftmax(float* __restrict__ out)
{
    const int r = blockIdx.x, tid = threadIdx.x;
    float4* row4 = (float4*)(out + (size_t)r * VV);
    float m = NEG_INF, s = 0.0f;
    for (int v = tid; v < VV / 4; v += 512) {
        float4 l4 = row4[v];
        float lm = fmaxf(fmaxf(l4.x, l4.y), fmaxf(l4.z, l4.w));
        if (lm > m) { s = s * expf(m - lm); m = lm; }
        s += expf(l4.x - m) + expf(l4.y - m) + expf(l4.z - m) + expf(l4.w - m);
    }
    __shared__ float smx[512], ssm[512];
    smx[tid] = m; ssm[tid] = s;
    __syncthreads();
#pragma unroll
    for (int o = 256; o > 0; o >>= 1) {
        if (tid < o) {
            float m2 = fmaxf(smx[tid], smx[tid + o]);
            ssm[tid] = ssm[tid] * expf(smx[tid] - m2) + ssm[tid + o] * expf(smx[tid + o] - m2);
            smx[tid] = m2;
        }
        __syncthreads();
    }
    float M = smx[0], inv = 1.0f / ssm[0];
    for (int v = tid; v < VV / 4; v += 512) {
        float4 l4 = row4[v];
        l4.x = expf(l4.x - M) * inv;
        l4.y = expf(l4.y - M) * inv;
        l4.z = expf(l4.z - M) * inv;
        l4.w = expf(l4.w - M) * inv;
        row4[v] = l4;
    }
}

// ---------------- host ----------------
extern "C" void kernel_launch(void* const* d_in, const int* in_sizes, int n_in,
                              void* d_out, int out_size)
{
    const int*   ids  = (const int*)d_in[0];
    const float* h0   = (const float*)d_in[1];
    const float* c0   = (const float*)d_in[2];
    const float* enc  = (const float*)d_in[3];
    const unsigned char* mask = (const unsigned char*)d_in[4];
    const float* emb  = (const float*)d_in[5];
    const float* Wr   = (const float*)d_in[6];
    const float* br   = (const float*)d_in[7];
    const float* Wih  = (const float*)d_in[8];
    const float* Whh  = (const float*)d_in[9];
    const float* bih  = (const float*)d_in[10];
    const float* bhh  = (const float*)d_in[11];
    const float* Wh_a = (const float*)d_in[12];
    const float* Ws_a = (const float*)d_in[13];
    const float* bs_a = (const float*)d_in[14];
    const float* v_a  = (const float*)d_in[15];
    const float* wh_p = (const float*)d_in[16];
    const float* ws_p = (const float*)d_in[17];
    const float* wx_p = (const float*)d_in[18];
    const float* bx_p = (const float*)d_in[19];
    const float* Wvr  = (const float*)d_in[20];
    const float* bvr  = (const float*)d_in[21];
    const float* Wvo  = (const float*)d_in[22];
    const float* bvo  = (const float*)d_in[23];
    float* out = (float*)d_out;

    float *encf = nullptr, *vredp = nullptr, *Wfp = nullptr;
    __nv_bfloat16 *vredbf = nullptr, *wvobf = nullptr, *encbf = nullptr, *whabf = nullptr;
    cudaGetSymbolAddress((void**)&encf,   g_enc_feat);
    cudaGetSymbolAddress((void**)&vredp,  g_vred);
    cudaGetSymbolAddress((void**)&Wfp,    g_Wf);
    cudaGetSymbolAddress((void**)&vredbf, g_vred_bf);
    cudaGetSymbolAddress((void**)&wvobf,  g_Wvo_bf);
    cudaGetSymbolAddress((void**)&encbf,  g_enc_bf);
    cudaGetSymbolAddress((void**)&whabf,  g_Wha_bf);

    cudaFuncSetAttribute(k_persistent, cudaFuncAttributeMaxDynamicSharedMemorySize,
                         (int)sizeof(Smem));

    // prep: barrier reset, fused biases, folded pgen vector, h/c/ctx init
    k_prep<<<8, 256>>>(Wih, br, bih, bhh, Wr, wx_p, bx_p);
    k_init<<<64, 256>>>(h0, c0);

    // Wf = Wih[1024,256] @ Wr[256,640] (kept fp32)
    sgemm_abn<<<dim3(5, 8), 256>>>(Wih, Wr, Wfp, 1024, 640, 256);

    // enc_feat = enc @ Wh_a^T via bf16 tensor cores
    k_cvt<<<(BB * SS * H2 / 4 + 255) / 256, 256>>>(enc, encbf, BB * SS * H2 / 4);
    k_cvt<<<(HH * H2 / 4 + 255) / 256, 256>>>(Wh_a, whabf, HH * H2 / 4);
    hgemm_nt<<<dim3(2, 100), 256>>>(encbf, whabf, nullptr, encf, BB * SS, HH, H2);

    // Wvo fp32 -> bf16 (independent of the recurrence)
    k_cvt<<<(VV * HH / 4 + 255) / 256, 256>>>(Wvo, wvobf, VV * HH / 4);

    // full 64-step recurrence in one persistent kernel
    k_persistent<<<NB, TPB, sizeof(Smem)>>>(ids, emb, enc, mask, Whh, Ws_a, bs_a, v_a,
                                            wh_p, ws_p, Wvr, bvr, out);

    // vocab projection (bf16 tensor cores) + softmax
    k_cvt<<<(BB * TT * HH / 4 + 255) / 256, 256>>>(vredp, vredbf, BB * TT * HH / 4);
    hgemm_nt<<<dim3(391, 16), 256>>>(vredbf, wvobf, bvo, out, BB * TT, VV, HH);
    k_vsoftmax<<<BB * TT, 512>>>(out);
}

// round 14
// speedup vs baseline: 4.9965x; 1.0221x over previous
#include <cuda_runtime.h>
#include <cuda_bf16.h>
#include <math.h>
#include <cstdint>

#define BB 32
#define TT 64
#define SS 400
#define HH 256
#define EE 128
#define VV 50000
#define H2 512

#define NB  148
#define TPB 512
#define SRED_P 44

// d_out layout (fp32): vocab_dists[B,T,V], attn[B,T,S], pgen[B,T,1], h[B,H], c[B,H]
#define OFF_ATTN 102400000ull
#define OFF_PG   103219200ull
#define OFF_H    103221248ull
#define OFF_C    103229440ull

// ---------------- scratch ----------------
__device__ unsigned g_cnt;
__device__ float g_Wf[1024 * 640];      // Wih @ Wr  [4H, 640]  (fp32 on purpose)
__device__ float g_bf[1024];            // bih + bhh + Wih @ br
__device__ float g_wxr[641];            // Wr^T @ wx_p ; [640] = wx_p.br + bx_p
__device__ float g_enc_feat[BB * SS * HH];
__device__ float g_h[2][BB * HH];
__device__ float g_c[2][BB * HH];
__device__ float g_ctx[BB * H2];
__device__ float g_dec[BB * HH];
__device__ float g_scores[BB * SS];
__device__ __nv_bfloat16 g_vred_bf[BB * TT * HH];   // rows r = b*T+t, written by persistent
__device__ __nv_bfloat16 g_Wvo_bf[VV * HH];
__device__ __nv_bfloat16 g_enc_bf[BB * SS * H2];
__device__ __nv_bfloat16 g_Wha_bf[HH * H2];

__device__ __forceinline__ float sigf(float v) { return 1.0f / (1.0f + expf(-v)); }
__device__ __forceinline__ float ftanh(float x) {
    float r; asm("tanh.approx.f32 %0, %1;" : "=f"(r) : "f"(x)); return r;
}
#define NEG_INF __int_as_float(0xff800000)

// ---------------- packed fp32x2 FMA helpers ----------------
__device__ __forceinline__ void fma2(unsigned long long& d,
                                     unsigned long long a, unsigned long long b) {
    asm("fma.rn.f32x2 %0, %1, %2, %0;" : "+l"(d) : "l"(a), "l"(b));
}
__device__ __forceinline__ float unpack_add(unsigned long long v) {
    float lo = __uint_as_float((unsigned)(v & 0xffffffffull));
    float hi = __uint_as_float((unsigned)(v >> 32));
    return lo + hi;
}
__device__ __forceinline__ void dot16p(unsigned long long& acc,
                                       const float* __restrict__ a,
                                       const float* __restrict__ w) {
    ulonglong2 A0 = *(const ulonglong2*)(a + 0), A1 = *(const ulonglong2*)(a + 4);
    ulonglong2 A2 = *(const ulonglong2*)(a + 8), A3 = *(const ulonglong2*)(a + 12);
    ulonglong2 W0 = *(const ulonglong2*)(w + 0), W1 = *(const ulonglong2*)(w + 4);
    ulonglong2 W2 = *(const ulonglong2*)(w + 8), W3 = *(const ulonglong2*)(w + 12);
    fma2(acc, A0.x, W0.x); fma2(acc, A0.y, W0.y);
    fma2(acc, A1.x, W1.x); fma2(acc, A1.y, W1.y);
    fma2(acc, A2.x, W2.x); fma2(acc, A2.y, W2.y);
    fma2(acc, A3.x, W3.x); fma2(acc, A3.y, W3.y);
}

__device__ __forceinline__ float wredmax(float v) {
#pragma unroll
    for (int o = 16; o > 0; o >>= 1) v = fmaxf(v, __shfl_xor_sync(0xffffffffu, v, o));
    return v;
}
__device__ __forceinline__ float wredsum(float v) {
#pragma unroll
    for (int o = 16; o > 0; o >>= 1) v += __shfl_xor_sync(0xffffffffu, v, o);
    return v;
}

// ---------------- grid-wide software barrier ----------------
__device__ __forceinline__ void gbarrier(unsigned& target) {
    __syncthreads();
    if (threadIdx.x == 0) {
        unsigned* pc = &g_cnt;
        asm volatile("red.release.gpu.global.add.u32 [%0], 1;" :: "l"(pc) : "memory");
        target += NB;
        unsigned v;
        asm volatile("ld.acquire.gpu.global.u32 %0, [%1];" : "=r"(v) : "l"(pc) : "memory");
        while (v < target) {
            asm volatile("nanosleep.u32 128;");
            asm volatile("ld.acquire.gpu.global.u32 %0, [%1];" : "=r"(v) : "l"(pc) : "memory");
        }
    }
    __syncthreads();
}

// ---------------- prep ----------------
__global__ void k_prep(const float* __restrict__ Wih, const float* __restrict__ br,
                       const float* __restrict__ bih, const float* __restrict__ bhh,
                       const float* __restrict__ Wr, const float* __restrict__ wxp,
                       const float* __restrict__ bxp) {
    int p = blockIdx.x, tid = threadIdx.x;
    if (p == 0 && tid == 0) g_cnt = 0;
    if (p < 4) {
        int n = p * 256 + tid;
        float acc = bih[n] + bhh[n];
        const float* w = Wih + (size_t)n * 256;
        for (int m = 0; m < 256; m++) acc += w[m] * br[m];
        g_bf[n] = acc;
    } else if (p < 7) {
        int k = (p - 4) * 256 + tid;
        if (k < 640) {
            float acc = 0.f;
            for (int m = 0; m < 256; m++) acc += wxp[m] * Wr[(size_t)m * 640 + k];
            g_wxr[k] = acc;
        }
    } else if (tid == 0) {
        float acc = bxp[0];
        for (int m = 0; m < 256; m++) acc += wxp[m] * br[m];
        g_wxr[640] = acc;
    }
}

__global__ void k_init(const float* __restrict__ h0, const float* __restrict__ c0) {
    int i = blockIdx.x * 256 + threadIdx.x;
    if (i < BB * HH) { g_h[0][i] = h0[i]; g_c[0][i] = c0[i]; }
    if (i < BB * H2) g_ctx[i] = 0.0f;
}

// ---------------- fp32 -> bf16 ----------------
__global__ void k_cvt(const float* __restrict__ in, __nv_bfloat16* __restrict__ out, int n4)
{
    int i = blockIdx.x * 256 + threadIdx.x;
    if (i < n4) {
        float4 v = ((const float4*)in)[i];
        ((__nv_bfloat162*)out)[i * 2 + 0] = __floats2bfloat162_rn(v.x, v.y);
        ((__nv_bfloat162*)out)[i * 2 + 1] = __floats2bfloat162_rn(v.z, v.w);
    }
}

// ---------------- fp32 GEMM (Wf precompute): C[M,N] = A[M,K] @ Bn[K,N] ----------------
__global__ __launch_bounds__(256) void sgemm_abn(
    const float* __restrict__ A, const float* __restrict__ Bn,
    float* __restrict__ C, int M, int N, int K)
{
    __shared__ float As[8][128];
    __shared__ float Bs[8][128];
    const int tid = threadIdx.x;
    const int row0 = blockIdx.y << 7;
    const int col0 = blockIdx.x << 7;
    const int tr = (tid >> 4) << 3;
    const int tc = (tid & 15) << 3;
    float acc[8][8];
#pragma unroll
    for (int i = 0; i < 8; i++)
#pragma unroll
        for (int j = 0; j < 8; j++) acc[i][j] = 0.0f;
    const int lr = tid >> 1, lk = (tid & 1) << 2;
    const int blc = (tid & 31) << 2, blk = tid >> 5;
    for (int k0 = 0; k0 < K; k0 += 8) {
        float4 av = *(const float4*)&A[(size_t)(row0 + lr) * K + k0 + lk];
        As[lk + 0][lr] = av.x; As[lk + 1][lr] = av.y; As[lk + 2][lr] = av.z; As[lk + 3][lr] = av.w;
        float4 bv = *(const float4*)&Bn[(size_t)(k0 + blk) * N + col0 + blc];
        Bs[blk][blc + 0] = bv.x; Bs[blk][blc + 1] = bv.y; Bs[blk][blc + 2] = bv.z; Bs[blk][blc + 3] = bv.w;
        __syncthreads();
#pragma unroll
        for (int kk = 0; kk < 8; kk++) {
            float4 a0 = *(const float4*)&As[kk][tr];
            float4 a1 = *(const float4*)&As[kk][tr + 4];
            float4 b0 = *(const float4*)&Bs[kk][tc];
            float4 b1 = *(const float4*)&Bs[kk][tc + 4];
            float a[8] = {a0.x, a0.y, a0.z, a0.w, a1.x, a1.y, a1.z, a1.w};
            float b[8] = {b0.x, b0.y, b0.z, b0.w, b1.x, b1.y, b1.z, b1.w};
#pragma unroll
            for (int i = 0; i < 8; i++)
#pragma unroll
                for (int j = 0; j < 8; j++) acc[i][j] += a[i] * b[j];
        }
        __syncthreads();
    }
#pragma unroll
    for (int i = 0; i < 8; i++) {
        size_t r = row0 + tr + i;
#pragma unroll
        for (int j = 0; j < 8; j++)
            C[r * (size_t)N + col0 + tc + j] = acc[i][j];
    }
}

// ================= bf16 tensor-core GEMM: C[M,N] = A[M,K] @ W[N,K]^T (+bias) =============
__device__ __forceinline__ void ldm_x4(unsigned* r, const void* p) {
    unsigned a = (unsigned)__cvta_generic_to_shared(p);
    asm volatile("ldmatrix.sync.aligned.m8n8.x4.shared.b16 {%0,%1,%2,%3}, [%4];"
        : "=r"(r[0]), "=r"(r[1]), "=r"(r[2]), "=r"(r[3]) : "r"(a));
}
__device__ __forceinline__ void mma16816(float* c, const unsigned* a, unsigned b0, unsigned b1) {
    asm volatile("mma.sync.aligned.m16n8k16.row.col.f32.bf16.bf16.f32 "
        "{%0,%1,%2,%3}, {%4,%5,%6,%7}, {%8,%9}, {%0,%1,%2,%3};"
        : "+f"(c[0]), "+f"(c[1]), "+f"(c[2]), "+f"(c[3])
        : "r"(a[0]), "r"(a[1]), "r"(a[2]), "r"(a[3]), "r"(b0), "r"(b1));
}

__global__ __launch_bounds__(256) void hgemm_nt(
    const __nv_bfloat16* __restrict__ A,
    const __nv_bfloat16* __restrict__ W,
    const float* __restrict__ bias, float* __restrict__ C,
    int M, int N, int K)
{
    __shared__ __nv_bfloat16 As[128][72];
    __shared__ __nv_bfloat16 Ws[128][72];
    const int n0 = blockIdx.x << 7;
    const int m0 = blockIdx.y << 7;
    const int tid = threadIdx.x;
    const int warp = tid >> 5, lane = tid & 31;
    const int wm = (warp & 1) << 6;
    const int wn = (warp >> 1) << 5;

    float acc[4][4][4];
#pragma unroll
    for (int i = 0; i < 4; i++)
#pragma unroll
        for (int j = 0; j < 4; j++)
#pragma unroll
            for (int q = 0; q < 4; q++) acc[i][j][q] = 0.f;

    for (int k0 = 0; k0 < K; k0 += 64) {
#pragma unroll
        for (int r = 0; r < 4; r++) {
            int i = tid + r * 256;
            int row = i >> 3, c = (i & 7) * 8;
            *(uint4*)&As[row][c] = *(const uint4*)&A[(size_t)(m0 + row) * K + k0 + c];
            uint4 v = make_uint4(0u, 0u, 0u, 0u);
            if (n0 + row < N)
                v = *(const uint4*)&W[(size_t)(n0 + row) * K + k0 + c];
            *(uint4*)&Ws[row][c] = v;
        }
        __syncthreads();
#pragma unroll
        for (int ks = 0; ks < 64; ks += 16) {
            unsigned af[4][4];
#pragma unroll
            for (int ma = 0; ma < 4; ma++)
                ldm_x4(af[ma], &As[wm + ma * 16 + (lane & 15)][ks + (lane >> 4) * 8]);
            unsigned bfr[2][4];
#pragma unroll
            for (int nb = 0; nb < 2; nb++)
                ldm_x4(bfr[nb], &Ws[wn + nb * 16 + (lane & 15)][ks + (lane >> 4) * 8]);
#pragma unroll
            for (int ma = 0; ma < 4; ma++)
#pragma unroll
                for (int na = 0; na < 4; na++)
                    mma16816(acc[ma][na], af[ma],
                             bfr[na >> 1][na & 1], bfr[na >> 1][2 + (na & 1)]);
        }
        __syncthreads();
    }
#pragma unroll
    for (int ma = 0; ma < 4; ma++) {
        int r0 = m0 + wm + ma * 16 + (lane >> 2);
#pragma unroll
        for (int na = 0; na < 4; na++) {
            int c = n0 + wn + na * 8 + (lane & 3) * 2;
            if (c < N) {
                float b0 = bias ? bias[c] : 0.f;
                float b1 = bias ? bias[c + 1] : 0.f;
                float2 v0 = make_float2(acc[ma][na][0] + b0, acc[ma][na][1] + b1);
                float2 v1 = make_float2(acc[ma][na][2] + b0, acc[ma][na][3] + b1);
                *(float2*)&C[(size_t)r0 * N + c] = v0;
                *(float2*)&C[(size_t)(r0 + 8) * N + c] = v1;
            }
        }
    }
}

// ================= persistent recurrence kernel =================
struct Smem {
    float sA[7 * 32 * 132];   // 118 KB
    float sred[64 * SRED_P];  // gates partials [0..31] + vred partials [36..43]
    float sat[SS];
    float red[64];
    float spart[512];
    float spg[512];
};

__device__ __forceinline__ void pgen_block(
    Smem* sm, int tp, const int* __restrict__ ids, const float* __restrict__ emb,
    const float* __restrict__ hn, const float* __restrict__ cn,
    const float* __restrict__ whp, const float* __restrict__ wsp,
    float* __restrict__ dout, int p)
{
    const int tid = threadIdx.x;
    const int half = tid >> 8, lt = tid & 255;
    const int b = (p - 128) * 2 + half;
    float acc = 0.f;
    for (int k = lt; k < 512; k += 256) {
        float sv = (k < 256) ? hn[b * HH + k] : cn[b * HH + k - 256];
        acc += whp[k] * g_ctx[b * H2 + k] + wsp[k] * sv;
    }
    int id = ids[b * TT + tp];
    for (int k = lt; k < 640; k += 256) {
        float av = (k < 128) ? emb[(size_t)id * EE + k] : g_ctx[b * H2 + k - 128];
        acc += g_wxr[k] * av;
    }
    sm->spg[tid] = acc;
    __syncthreads();
#pragma unroll
    for (int o = 128; o > 0; o >>= 1) {
        if (lt < o) sm->spg[half * 256 + lt] += sm->spg[half * 256 + lt + o];
        __syncthreads();
    }
    if (lt == 0)
        dout[OFF_PG + (size_t)b * TT + tp] = sigf(sm->spg[half * 256] + g_wxr[640]);
    __syncthreads();
}

__global__ __launch_bounds__(TPB, 1) void k_persistent(
    const int* __restrict__ ids, const float* __restrict__ emb,
    const float* __restrict__ enc, const unsigned char* __restrict__ mask,
    const float* __restrict__ Whh, const float* __restrict__ Wsa,
    const float* __restrict__ bsa, const float* __restrict__ va,
    const float* __restrict__ whp, const float* __restrict__ wsp,
    const float* __restrict__ Wvr, const float* __restrict__ bvr,
    float* __restrict__ dout)
{
    extern __shared__ char smraw[];
    Smem* sm = (Smem*)smraw;
    const int p = blockIdx.x, tid = threadIdx.x;
    const int b = tid & 31, jl = (tid >> 5) & 1, kq = tid >> 6;
    unsigned target = 0;

    for (int t = 0; t < TT; t++) {
        const float* hin = g_h[t & 1];
        const float* cin = g_c[t & 1];
        float* hout = g_h[(t + 1) & 1];
        float* cout = g_c[(t + 1) & 1];

        // ============ P1: stage [emb|ctx|h]; vred(t-1) + gates(t), one reduction ====
        if (p < 128) {
            const int j = p * 2 + jl;
#pragma unroll
            for (int r = 0; r < 14; r++) {
                int idx = tid + r * 512;
                int bb = idx / 224;
                int q = idx - bb * 224;
                float4 v;
                if (q < 32)       v = ((const float4*)(emb + (size_t)ids[bb * TT + t] * EE))[q];
                else if (q < 160) v = ((const float4*)(g_ctx + bb * H2))[q - 32];
                else              v = ((const float4*)(hin + bb * HH))[q - 160];
                int k = q * 4, cch = k >> 7, kk = k & 127;
                *(float4*)&sm->sA[(cch * 32 + bb) * 132 + kk] = v;
            }
            __syncthreads();

            // vred(t-1): remap vred-k -> gates chunks (h: 5,6 ; ctx: 1..4)
            unsigned long long accv = 0ull;
            if (t > 0) {
                const float* wv = Wvr + (size_t)j * 768;
#pragma unroll
                for (int cv = 0; cv < 6; cv++) {
                    int gc = (cv < 2) ? (5 + cv) : (cv - 1);
                    dot16p(accv, &sm->sA[(gc * 32 + b) * 132 + kq * 16],
                           wv + cv * 128 + kq * 16);
                }
            }
            // gates(t)
            unsigned long long ag0 = 0ull, ag1 = 0ull, ag2 = 0ull, ag3 = 0ull;
#pragma unroll
            for (int cch = 0; cch < 7; cch++) {
                const float* av = &sm->sA[(cch * 32 + b) * 132 + kq * 16];
                if (cch < 5) {
                    int kg = cch * 128 + kq * 16;
                    dot16p(ag0, av, &g_Wf[(size_t)(0 * 256 + j) * 640 + kg]);
                    dot16p(ag1, av, &g_Wf[(size_t)(1 * 256 + j) * 640 + kg]);
                    dot16p(ag2, av, &g_Wf[(size_t)(2 * 256 + j) * 640 + kg]);
                    dot16p(ag3, av, &g_Wf[(size_t)(3 * 256 + j) * 640 + kg]);
                } else {
                    int kh = cch * 128 + kq * 16 - 640;
                    dot16p(ag0, av, &Whh[(size_t)(0 * 256 + j) * 256 + kh]);
                    dot16p(ag1, av, &Whh[(size_t)(1 * 256 + j) * 256 + kh]);
                    dot16p(ag2, av, &Whh[(size_t)(2 * 256 + j) * 256 + kh]);
                    dot16p(ag3, av, &Whh[(size_t)(3 * 256 + j) * 256 + kh]);
                }
            }
            {
                float* r = &sm->sred[(jl * 32 + b) * SRED_P];
                r[kq * 4 + 0] = unpack_add(ag0); r[kq * 4 + 1] = unpack_add(ag1);
                r[kq * 4 + 2] = unpack_add(ag2); r[kq * 4 + 3] = unpack_add(ag3);
                if (t > 0) r[36 + kq] = unpack_add(accv);
            }
            __syncthreads();
            if (tid < 64) {
                int bb2 = tid & 31, jjl = tid >> 5, jj = p * 2 + jjl;
                const float* rr = &sm->sred[(jjl * 32 + bb2) * SRED_P];
                float s0 = 0.f, s1 = 0.f, s2 = 0.f, s3 = 0.f;
#pragma unroll
                for (int q = 0; q < 8; q++) {
                    s0 += rr[q * 4 + 0]; s1 += rr[q * 4 + 1];
                    s2 += rr[q * 4 + 2]; s3 += rr[q * 4 + 3];
                }
                if (t > 0) {
                    float sv = ((rr[36] + rr[37]) + (rr[38] + rr[39]))
                             + ((rr[40] + rr[41]) + (rr[42] + rr[43]));
                    g_vred_bf[((size_t)bb2 * TT + (t - 1)) * HH + jj] =
                        __float2bfloat16(sv + bvr[jj]);
                }
                float gi = s0 + g_bf[jj];
                float gf = s1 + g_bf[256 + jj];
                float gg = s2 + g_bf[512 + jj];
                float go = s3 + g_bf[768 + jj];
                float co = cin[bb2 * HH + jj];
                float cn = sigf(gf) * co + sigf(gi) * tanhf(gg);
                float hn = sigf(go) * tanhf(cn);
                cout[bb2 * HH + jj] = cn;
                hout[bb2 * HH + jj] = hn;
            }
        } else if (p < 144) {
            if (t > 0) pgen_block(sm, t - 1, ids, emb, hin, cin, whp, wsp, dout, p);
        }
        gbarrier(target);

        // ============ P2: dec = [h|c] @ Wsa^T + bsa ================================
        if (p < 128) {
            const int j = p * 2 + jl;
#pragma unroll
            for (int r = 0; r < 8; r++) {
                int idx = tid + r * 512;
                int bb = idx >> 7, q = idx & 127;
                float4 v = (q < 64) ? ((const float4*)(hout + bb * HH))[q]
                                    : ((const float4*)(cout + bb * HH))[q - 64];
                int k = q * 4, cch = k >> 7, kk = k & 127;
                *(float4*)&sm->sA[(cch * 32 + bb) * 132 + kk] = v;
            }
            __syncthreads();
            unsigned long long acc = 0ull;
#pragma unroll
            for (int cch = 0; cch < 4; cch++)
                dot16p(acc, &sm->sA[(cch * 32 + b) * 132 + kq * 16],
                       Wsa + (size_t)j * 512 + cch * 128 + kq * 16);
            sm->sred[(jl * 32 + b) * SRED_P + kq] = unpack_add(acc);
            __syncthreads();
            if (tid < 64) {
                int bb2 = tid & 31, jjl = tid >> 5, jj = p * 2 + jjl;
                const float* r = &sm->sred[(jjl * 32 + bb2) * SRED_P];
                float s = ((r[0] + r[1]) + (r[2] + r[3])) + ((r[4] + r[5]) + (r[6] + r[7]));
                g_dec[bb2 * HH + jj] = s + bsa[jj];
            }
        }
        gbarrier(target);

        // ============ P3: scores ===================================================
        {
            const int w = tid >> 5, lane = tid & 31;
#pragma unroll
            for (int i = 0; i < 6; i++) {
                int u = p * 16 + w + i * (NB * 16);
                if (u < BB * SS) {
                    int bu = u / SS;
                    const float4* ef = (const float4*)(g_enc_feat + (size_t)u * HH);
                    const float4* dp = (const float4*)(g_dec + bu * HH);
                    const float4* vp = (const float4*)va;
                    float acc = 0.f;
#pragma unroll
                    for (int h = 0; h < 2; h++) {
                        int ix = lane + h * 32;
                        float4 e = ef[ix], d = dp[ix], v = vp[ix];
                        acc += v.x * ftanh(e.x + d.x) + v.y * ftanh(e.y + d.y)
                             + v.z * ftanh(e.z + d.z) + v.w * ftanh(e.w + d.w);
                    }
#pragma unroll
                    for (int o = 16; o > 0; o >>= 1) acc += __shfl_xor_sync(0xffffffffu, acc, o);
                    if (lane == 0) g_scores[u] = mask[u] ? NEG_INF : acc;
                }
            }
        }
        gbarrier(target);

        // ============ P4: softmax + ctx ============================================
        if (p < 128) {
            const int bq = p >> 2, ch = p & 3;
            const int w = tid >> 5, lane = tid & 31;
            float sc = (tid < SS) ? g_scores[bq * SS + tid] : NEG_INF;
            float wm = wredmax(sc);
            if (lane == 0) sm->red[w] = wm;
            __syncthreads();
            if (w == 0) {
                float m2 = (lane < 16) ? sm->red[lane] : NEG_INF;
                m2 = wredmax(m2);
                if (lane == 0) sm->red[32] = m2;
            }
            __syncthreads();
            float m = sm->red[32];
            float e = (tid < SS) ? __expf(sc - m) : 0.f;
            float wsv = wredsum(e);
            if (lane == 0) sm->red[w] = wsv;
            __syncthreads();
            if (w == 0) {
                float s2 = (lane < 16) ? sm->red[lane] : 0.f;
                s2 = wredsum(s2);
                if (lane == 0) sm->red[33] = 1.0f / s2;
            }
            __syncthreads();
            float inv = sm->red[33];
            if (tid < SS) {
                float a = e * inv;
                sm->sat[tid] = a;
                if (ch == 0) dout[OFF_ATTN + ((size_t)bq * TT + t) * SS + tid] = a;
            }
            __syncthreads();
            const int d = tid & 127, sg = tid >> 7;
            const float* ep = enc + ((size_t)bq * SS + sg * 100) * H2 + ch * 128 + d;
            float acc0 = 0.f, acc1 = 0.f;
#pragma unroll 10
            for (int s = 0; s < 100; s += 2) {
                acc0 += sm->sat[sg * 100 + s] * ep[(size_t)s * H2];
                acc1 += sm->sat[sg * 100 + s + 1] * ep[(size_t)(s + 1) * H2];
            }
            sm->spart[sg * 128 + d] = acc0 + acc1;
            __syncthreads();
            if (tid < 128) {
                float v = (sm->spart[tid] + sm->spart[128 + tid])
                        + (sm->spart[256 + tid] + sm->spart[384 + tid]);
                g_ctx[bq * H2 + ch * 128 + tid] = v;
            }
        }
        gbarrier(target);
    }

    // ============ tail: vred(63), pgen(63), final h/c ==============================
    const float* hf = g_h[0];
    const float* cf = g_c[0];
    if (p < 128) {
        const int j = p * 2 + jl;
#pragma unroll
        for (int r = 0; r < 12; r++) {
            int idx = tid + r * 512;
            int bb = idx / 192;
            int q = idx - bb * 192;
            float4 v = (q < 64) ? ((const float4*)(hf + bb * HH))[q]
                                : ((const float4*)(g_ctx + bb * H2))[q - 64];
            int k = q * 4, cch = k >> 7, kk = k & 127;
            *(float4*)&sm->sA[(cch * 32 + bb) * 132 + kk] = v;
        }
        __syncthreads();
        unsigned long long acc = 0ull;
#pragma unroll
        for (int cv = 0; cv < 6; cv++)
            dot16p(acc, &sm->sA[(cv * 32 + b) * 132 + kq * 16],
                   Wvr + (size_t)j * 768 + cv * 128 + kq * 16);
        sm->sred[(jl * 32 + b) * SRED_P + kq] = unpack_add(acc);
        __syncthreads();
        if (tid < 64) {
            int bb2 = tid & 31, jjl = tid >> 5, jj = p * 2 + jjl;
            const float* r = &sm->sred[(jjl * 32 + bb2) * SRED_P];
            float s = ((r[0] + r[1]) + (r[2] + r[3])) + ((r[4] + r[5]) + (r[6] + r[7]));
            g_vred_bf[((size_t)bb2 * TT + (TT - 1)) * HH + jj] =
                __float2bfloat16(s + bvr[jj]);
        }
    } else if (p < 144) {
        pgen_block(sm, TT - 1, ids, emb, hf, cf, whp, wsp, dout, p);
    } else {
        for (int i0 = (p - 144) * 2048 + tid; i0 < (p - 143) * 2048; i0 += TPB) {
            dout[OFF_H + i0] = hf[i0];
            dout[OFF_C + i0] = cf[i0];
        }
    }
}

// ---------------- row softmax over V: register-resident single pass ----------------
// one row per block, 256 threads, 49 float4/thread (logits live in registers)
__global__ __launch_bounds__(256) void k_vsoftmax(float* __restrict__ out)
{
    const int r = blockIdx.x, tid = threadIdx.x;
    float4* row4 = (float4*)(out + (size_t)r * VV);
    float4 v[49];
    float m = NEG_INF;
#pragma unroll
    for (int i = 0; i < 49; i++) {
        int idx = tid + i * 256;
        if (idx < VV / 4) {
            v[i] = row4[idx];
            m = fmaxf(m, fmaxf(fmaxf(v[i].x, v[i].y), fmaxf(v[i].z, v[i].w)));
        }
    }
    __shared__ float sred[8];
    __shared__ float sbc[2];
    m = wredmax(m);
    if ((tid & 31) == 0) sred[tid >> 5] = m;
    __syncthreads();
    if (tid < 32) {
        float mm = (tid < 8) ? sred[tid] : NEG_INF;
        mm = wredmax(mm);
        if (tid == 0) sbc[0] = mm;
    }
    __syncthreads();
    float M = sbc[0];
    float s = 0.f;
#pragma unroll
    for (int i = 0; i < 49; i++) {
        int idx = tid + i * 256;
        if (idx < VV / 4) {
            v[i].x = __expf(v[i].x - M);
            v[i].y = __expf(v[i].y - M);
            v[i].z = __expf(v[i].z - M);
            v[i].w = __expf(v[i].w - M);
            s += (v[i].x + v[i].y) + (v[i].z + v[i].w);
        }
    }
    s = wredsum(s);
    if ((tid & 31) == 0) sred[tid >> 5] = s;
    __syncthreads();
    if (tid < 32) {
        float ss = (tid < 8) ? sred[tid] : 0.f;
        ss = wredsum(ss);
        if (tid == 0) sbc[1] = 1.0f / ss;
    }
    __syncthreads();
    float inv = sbc[1];
#pragma unroll
    for (int i = 0; i < 49; i++) {
        int idx = tid + i * 256;
        if (idx < VV / 4) {
            v[i].x *= inv; v[i].y *= inv; v[i].z *= inv; v[i].w *= inv;
            row4[idx] = v[i];
        }
    }
}

// ---------------- host ----------------
extern "C" void kernel_launch(void* const* d_in, const int* in_sizes, int n_in,
                              void* d_out, int out_size)
{
    const int*   ids  = (const int*)d_in[0];
    const float* h0   = (const float*)d_in[1];
    const float* c0   = (const float*)d_in[2];
    const float* enc  = (const float*)d_in[3];
    const unsigned char* mask = (const unsigned char*)d_in[4];
    const float* emb  = (const float*)d_in[5];
    const float* Wr   = (const float*)d_in[6];
    const float* br   = (const float*)d_in[7];
    const float* Wih  = (const float*)d_in[8];
    const float* Whh  = (const float*)d_in[9];
    const float* bih  = (const float*)d_in[10];
    const float* bhh  = (const float*)d_in[11];
    const float* Wh_a = (const float*)d_in[12];
    const float* Ws_a = (const float*)d_in[13];
    const float* bs_a = (const float*)d_in[14];
    const float* v_a  = (const float*)d_in[15];
    const float* wh_p = (const float*)d_in[16];
    const float* ws_p = (const float*)d_in[17];
    const float* wx_p = (const float*)d_in[18];
    const float* bx_p = (const float*)d_in[19];
    const float* Wvr  = (const float*)d_in[20];
    const float* bvr  = (const float*)d_in[21];
    const float* Wvo  = (const float*)d_in[22];
    const float* bvo  = (const float*)d_in[23];
    float* out = (float*)d_out;

    float *encf = nullptr, *Wfp = nullptr;
    __nv_bfloat16 *vredbf = nullptr, *wvobf = nullptr, *encbf = nullptr, *whabf = nullptr;
    cudaGetSymbolAddress((void**)&encf,   g_enc_feat);
    cudaGetSymbolAddress((void**)&Wfp,    g_Wf);
    cudaGetSymbolAddress((void**)&vredbf, g_vred_bf);
    cudaGetSymbolAddress((void**)&wvobf,  g_Wvo_bf);
    cudaGetSymbolAddress((void**)&encbf,  g_enc_bf);
    cudaGetSymbolAddress((void**)&whabf,  g_Wha_bf);

    cudaFuncSetAttribute(k_persistent, cudaFuncAttributeMaxDynamicSharedMemorySize,
                         (int)sizeof(Smem));

    // prep: barrier reset, fused biases, folded pgen vector, h/c/ctx init
    k_prep<<<8, 256>>>(Wih, br, bih, bhh, Wr, wx_p, bx_p);
    k_init<<<64, 256>>>(h0, c0);

    // Wf = Wih[1024,256] @ Wr[256,640] (kept fp32)
    sgemm_abn<<<dim3(5, 8), 256>>>(Wih, Wr, Wfp, 1024, 640, 256);

    // enc_feat = enc @ Wh_a^T via bf16 tensor cores
    k_cvt<<<(BB * SS * H2 / 4 + 255) / 256, 256>>>(enc, encbf, BB * SS * H2 / 4);
    k_cvt<<<(HH * H2 / 4 + 255) / 256, 256>>>(Wh_a, whabf, HH * H2 / 4);
    hgemm_nt<<<dim3(2, 100), 256>>>(encbf, whabf, nullptr, encf, BB * SS, HH, H2);

    // Wvo fp32 -> bf16 (independent of the recurrence)
    k_cvt<<<(VV * HH / 4 + 255) / 256, 256>>>(Wvo, wvobf, VV * HH / 4);

    // full 64-step recurrence (writes g_vred_bf directly)
    k_persistent<<<NB, TPB, sizeof(Smem)>>>(ids, emb, enc, mask, Whh, Ws_a, bs_a, v_a,
                                            wh_p, ws_p, Wvr, bvr, out);

    // vocab projection (bf16 tensor cores) + softmax
    hgemm_nt<<<dim3(391, 16), 256>>>(vredbf, wvobf, bvo, out, BB * TT, VV, HH);
    k_vsoftmax<<<BB * TT, 256>>>(out);
}